// round 2
// baseline (speedup 1.0000x reference)
#include <cuda_runtime.h>
#include <cuda_bf16.h>
#include <math.h>

// Problem dimensions (fixed by the reference)
#define Bb 32
#define Nn 1024
#define Ee 512
#define Ff 300
#define HH 300
#define Vv 50001
#define NEGV (-9.0e15f)

constexpr int ROWS  = Bb * Nn;   // 32768 node rows
constexpr int EROWS = Bb * Ee;   // 16384 edge rows

// ---------------- scratch (device globals; no cudaMalloc allowed) ----------
__device__ float g_hidden[ROWS * Ff];
__device__ float g_proj  [ROWS * HH];
__device__ float g_x4    [ROWS * Ff];
__device__ float g_s1    [ROWS];
__device__ float g_sn    [ROWS];
__device__ float g_se    [EROWS];
__device__ float g_atte  [Bb * Ee * Nn];   // [B,E,N]
__device__ float g_HTt   [Bb * Nn * Ee];   // [B,N,E]
__device__ float g_edge  [EROWS * Ff];
__device__ float g_e4    [EROWS * Ff];
__device__ float g_attn  [Bb * Nn * Ee];   // [B,N,E]
__device__ float g_x1    [ROWS * Ff];
__device__ float g_xW    [ROWS * HH];
__device__ float g_sem   [ROWS * HH];
__device__ float g_comb  [ROWS * 2 * HH];
__device__ float g_hpre  [ROWS * HH];
__device__ float g_c     [2];

// ---------------- generic tiled SGEMM: C = A @ B (opt B^T), opt bias/ELU ---
// A: [M,K] row-major. B: [K,N] (TRANSB=false) or [N,K] (TRANSB=true).
// Batched via blockIdx.z with element strides sA/sB/sC.
template <bool TRANSB, int ACT>
__global__ void sgemm_k(const float* __restrict__ A, const float* __restrict__ B,
                        const float* __restrict__ bias, float* __restrict__ C,
                        int M, int N, int K, long sA, long sB, long sC)
{
    A += (long)blockIdx.z * sA;
    B += (long)blockIdx.z * sB;
    C += (long)blockIdx.z * sC;

    __shared__ float As[16][64];
    __shared__ float Bs[16][68];

    const int tid = threadIdx.x;
    const int tx = tid & 15, ty = tid >> 4;
    const int m0 = blockIdx.y * 64, n0 = blockIdx.x * 64;

    float acc[4][4];
#pragma unroll
    for (int i = 0; i < 4; ++i)
#pragma unroll
        for (int j = 0; j < 4; ++j) acc[i][j] = 0.f;

    for (int k0 = 0; k0 < K; k0 += 16) {
        // load A tile 64x16 -> As[k][m]
#pragma unroll
        for (int r = 0; r < 4; ++r) {
            int e  = tid + r * 256;
            int mm = e >> 4, kk = e & 15;
            int gm = m0 + mm, gk = k0 + kk;
            float v = 0.f;
            if (gm < M && gk < K) v = A[(long)gm * K + gk];
            As[kk][mm] = v;
        }
        // load B tile 16x64 -> Bs[k][n]
#pragma unroll
        for (int r = 0; r < 4; ++r) {
            int e = tid + r * 256;
            float v = 0.f;
            if (TRANSB) {
                int nn = e >> 4, kk = e & 15;
                int gn = n0 + nn, gk = k0 + kk;
                if (gn < N && gk < K) v = B[(long)gn * K + gk];
                Bs[kk][nn] = v;
            } else {
                int nn = e & 63, kk = e >> 6;
                int gn = n0 + nn, gk = k0 + kk;
                if (gk < K && gn < N) v = B[(long)gk * N + gn];
                Bs[kk][nn] = v;
            }
        }
        __syncthreads();
#pragma unroll
        for (int kk = 0; kk < 16; ++kk) {
            float a[4], b[4];
#pragma unroll
            for (int i = 0; i < 4; ++i) a[i] = As[kk][ty * 4 + i];
#pragma unroll
            for (int j = 0; j < 4; ++j) b[j] = Bs[kk][tx * 4 + j];
#pragma unroll
            for (int i = 0; i < 4; ++i)
#pragma unroll
                for (int j = 0; j < 4; ++j) acc[i][j] += a[i] * b[j];
        }
        __syncthreads();
    }

#pragma unroll
    for (int i = 0; i < 4; ++i) {
        int gm = m0 + ty * 4 + i;
        if (gm >= M) continue;
#pragma unroll
        for (int j = 0; j < 4; ++j) {
            int gn = n0 + tx * 4 + j;
            if (gn >= N) continue;
            float v = acc[i][j];
            if (bias) v += bias[gn];
            if (ACT == 1) v = (v > 0.f) ? v : expm1f(v);   // ELU
            C[(long)gm * N + gn] = v;
        }
    }
}

// ---------------- small kernels ---------------------------------------------
__global__ void gather_k(const int* __restrict__ idx,
                         const float* __restrict__ emb, float* __restrict__ out)
{
    int row = blockIdx.x;
    int id = idx[row];
    // defensive clamp: degrade to wrong-value instead of illegal access
    id = max(0, min(id, Vv - 1));
    const float* src = emb + (long)id * Ff;
    float* dst = out + (long)row * Ff;
    for (int c = threadIdx.x; c < Ff; c += blockDim.x) dst[c] = src[c];
}

__global__ void dot_scalar_k(const float* __restrict__ a, const float* __restrict__ b,
                             float* __restrict__ out, int K)
{
    __shared__ float sh[128];
    float s = 0.f;
    for (int c = threadIdx.x; c < K; c += 128) s += a[c] * b[c];
    sh[threadIdx.x] = s; __syncthreads();
    for (int o = 64; o > 0; o >>= 1) {
        if (threadIdx.x < o) sh[threadIdx.x] += sh[threadIdx.x + o];
        __syncthreads();
    }
    if (threadIdx.x == 0) *out = sh[0];
}

// s1[row] = leaky(c + X_row . v1), sn[row] = X_row . v2
__global__ void rowdots_k(const float* __restrict__ X, const float* __restrict__ v1,
                          const float* __restrict__ v2, const float* __restrict__ cptr,
                          float alpha, float* __restrict__ o1, float* __restrict__ o2, int K)
{
    int row = blockIdx.x;
    const float* x = X + (long)row * K;
    float s1 = 0.f, s2 = 0.f;
    for (int c = threadIdx.x; c < K; c += 128) {
        float xv = x[c];
        s1 += xv * v1[c];
        s2 += xv * v2[c];
    }
    __shared__ float r1[128], r2[128];
    r1[threadIdx.x] = s1; r2[threadIdx.x] = s2; __syncthreads();
    for (int o = 64; o > 0; o >>= 1) {
        if (threadIdx.x < o) { r1[threadIdx.x] += r1[threadIdx.x + o]; r2[threadIdx.x] += r2[threadIdx.x + o]; }
        __syncthreads();
    }
    if (threadIdx.x == 0) {
        float t = *cptr + r1[0];
        o1[row] = (t >= 0.f) ? t : alpha * t;
        o2[row] = r2[0];
    }
}

__global__ void rowdot_k(const float* __restrict__ X, const float* __restrict__ v,
                         float* __restrict__ o, int K)
{
    int row = blockIdx.x;
    const float* x = X + (long)row * K;
    float s = 0.f;
    for (int c = threadIdx.x; c < K; c += 128) s += x[c] * v[c];
    __shared__ float sh[128];
    sh[threadIdx.x] = s; __syncthreads();
    for (int o2 = 64; o2 > 0; o2 >>= 1) {
        if (threadIdx.x < o2) sh[threadIdx.x] += sh[threadIdx.x + o2];
        __syncthreads();
    }
    if (threadIdx.x == 0) o[row] = sh[0];
}

// att_e[b,e,:] = softmax_n( HT[b,e,n]>0 ? s1[b,n] : NEG )
__global__ void softmax_edge_k(const float* __restrict__ HT, const float* __restrict__ s1,
                               float* __restrict__ att)
{
    int b = blockIdx.y, e = blockIdx.x;
    const float* ht = HT + ((long)b * Ee + e) * Nn;
    const float* s  = s1 + (long)b * Nn;
    __shared__ float sv[Nn];
    __shared__ float red[256];
    int tid = threadIdx.x;

    float mx = -3.0e38f;
    for (int n = tid; n < Nn; n += 256) {
        float v = (ht[n] > 0.f) ? s[n] : NEGV;
        sv[n] = v;
        mx = fmaxf(mx, v);
    }
    red[tid] = mx; __syncthreads();
    for (int o = 128; o > 0; o >>= 1) {
        if (tid < o) red[tid] = fmaxf(red[tid], red[tid + o]);
        __syncthreads();
    }
    mx = red[0]; __syncthreads();

    float sum = 0.f;
    for (int n = tid; n < Nn; n += 256) {
        float ev = expf(sv[n] - mx);
        sv[n] = ev;
        sum += ev;
    }
    red[tid] = sum; __syncthreads();
    for (int o = 128; o > 0; o >>= 1) {
        if (tid < o) red[tid] += red[tid + o];
        __syncthreads();
    }
    float inv = 1.f / red[0];
    float* arow = att + ((long)b * Ee + e) * Nn;
    for (int n = tid; n < Nn; n += 256) arow[n] = sv[n] * inv;
}

// att_n[b,n,:] = softmax_e( HTt[b,n,e]>0 ? leaky(sn[b,n]+se[b,e]) : NEG )
__global__ void softmax_node_k(const float* __restrict__ HTt, const float* __restrict__ sn,
                               const float* __restrict__ se, float alpha,
                               float* __restrict__ att)
{
    int b = blockIdx.y, n = blockIdx.x;
    const float* ht  = HTt + ((long)b * Nn + n) * Ee;
    const float* seb = se + (long)b * Ee;
    float snv = sn[(long)b * Nn + n];
    __shared__ float sv[Ee];
    __shared__ float red[256];
    int tid = threadIdx.x;

    float mx = -3.0e38f;
    for (int e = tid; e < Ee; e += 256) {
        float t = snv + seb[e];
        t = (t >= 0.f) ? t : alpha * t;
        float v = (ht[e] > 0.f) ? t : NEGV;
        sv[e] = v;
        mx = fmaxf(mx, v);
    }
    red[tid] = mx; __syncthreads();
    for (int o = 128; o > 0; o >>= 1) {
        if (tid < o) red[tid] = fmaxf(red[tid], red[tid + o]);
        __syncthreads();
    }
    mx = red[0]; __syncthreads();

    float sum = 0.f;
    for (int e = tid; e < Ee; e += 256) {
        float ev = expf(sv[e] - mx);
        sv[e] = ev;
        sum += ev;
    }
    red[tid] = sum; __syncthreads();
    for (int o = 128; o > 0; o >>= 1) {
        if (tid < o) red[tid] += red[tid + o];
        __syncthreads();
    }
    float inv = 1.f / red[0];
    float* arow = att + ((long)b * Nn + n) * Ee;
    for (int e = tid; e < Ee; e += 256) arow[e] = sv[e] * inv;
}

// HT [B,E,N] -> HTt [B,N,E]
__global__ void transpose_k(const float* __restrict__ HT, float* __restrict__ HTt)
{
    __shared__ float t[32][33];
    int b  = blockIdx.z;
    int n0 = blockIdx.x * 32, e0 = blockIdx.y * 32;
    const float* src = HT + (long)b * Ee * Nn;
    float* dst = HTt + (long)b * Nn * Ee;
    int tx = threadIdx.x, ty = threadIdx.y;   // 32x8
#pragma unroll
    for (int i = 0; i < 32; i += 8)
        t[ty + i][tx] = src[(long)(e0 + ty + i) * Nn + n0 + tx];
    __syncthreads();
#pragma unroll
    for (int i = 0; i < 32; i += 8)
        dst[(long)(n0 + ty + i) * Ee + e0 + tx] = t[tx][ty + i];
}

__global__ void concat_k(const float* __restrict__ proj, const float* __restrict__ sem,
                         float* __restrict__ comb)
{
    int row = blockIdx.x;
    float* dst = comb + (long)row * (2 * HH);
    const float* p = proj + (long)row * HH;
    const float* s = sem + (long)row * HH;
    for (int c = threadIdx.x; c < HH; c += 128) {
        dst[c]      = p[c];
        dst[HH + c] = s[c];
    }
}

// tanh -> LayerNorm -> gate = sigmoid(h.A2 + b2) -> out = g*sem + (1-g)*proj
__global__ void final_k(const float* __restrict__ hpre, const float* __restrict__ proj,
                        const float* __restrict__ sem, const float* __restrict__ ln_g,
                        const float* __restrict__ ln_b, const float* __restrict__ A2,
                        const float* __restrict__ b2, float* __restrict__ out)
{
    int row = blockIdx.x;
    int tid = threadIdx.x;
    __shared__ float hs[HH];
    __shared__ float red[128];
    const float* hp = hpre + (long)row * HH;

    float s = 0.f;
    for (int c = tid; c < HH; c += 128) {
        float t = tanhf(hp[c]);
        hs[c] = t;
        s += t;
    }
    red[tid] = s; __syncthreads();
    for (int o = 64; o > 0; o >>= 1) {
        if (tid < o) red[tid] += red[tid + o];
        __syncthreads();
    }
    float mean = red[0] / (float)HH;
    __syncthreads();

    float vs = 0.f;
    for (int c = tid; c < HH; c += 128) { float d = hs[c] - mean; vs += d * d; }
    red[tid] = vs; __syncthreads();
    for (int o = 64; o > 0; o >>= 1) {
        if (tid < o) red[tid] += red[tid + o];
        __syncthreads();
    }
    float rstd = rsqrtf(red[0] / (float)HH + 1e-5f);
    __syncthreads();

    float gdot = 0.f;
    for (int c = tid; c < HH; c += 128) {
        float hn = (hs[c] - mean) * rstd * ln_g[c] + ln_b[c];
        gdot += hn * A2[c];
    }
    red[tid] = gdot; __syncthreads();
    for (int o = 64; o > 0; o >>= 1) {
        if (tid < o) red[tid] += red[tid + o];
        __syncthreads();
    }
    float gate = 1.f / (1.f + expf(-(red[0] + b2[0])));
    __syncthreads();

    const float* p = proj + (long)row * HH;
    const float* se = sem + (long)row * HH;
    float* o = out + (long)row * HH;
    for (int c = tid; c < HH; c += 128)
        o[c] = gate * se[c] + (1.f - gate) * p[c];
}

// ---------------- launcher ---------------------------------------------------
extern "C" void kernel_launch(void* const* d_in, const int* in_sizes, int n_in,
                              void* d_out, int out_size)
{
    const int*   inp  = (const int*)d_in[0];   // int32 (JAX x64 disabled)
    const float* HT   = (const float*)d_in[1];
    const float* emb  = (const float*)d_in[2];
    const float* Wp   = (const float*)d_in[3];
    const float* bp   = (const float*)d_in[4];
    const float* w2_1 = (const float*)d_in[5];
    const float* w3_1 = (const float*)d_in[6];
    const float* wc1  = (const float*)d_in[7];
    const float* a11  = (const float*)d_in[8];
    const float* a21  = (const float*)d_in[9];
    const float* W2t  = (const float*)d_in[10];
    const float* w2_2 = (const float*)d_in[11];
    const float* w3_2 = (const float*)d_in[12];
    const float* wc2  = (const float*)d_in[13];
    const float* a12  = (const float*)d_in[14];
    const float* a22  = (const float*)d_in[15];
    const float* A1   = (const float*)d_in[16];
    const float* b1   = (const float*)d_in[17];
    const float* ln_g = (const float*)d_in[18];
    const float* ln_b = (const float*)d_in[19];
    const float* A2   = (const float*)d_in[20];
    const float* b2   = (const float*)d_in[21];
    float* outp = (float*)d_out;

    float *hidden, *proj, *x4, *s1, *sn, *se, *atte, *HTt, *edge, *e4, *attn,
          *x1, *xW, *sem, *comb, *hpre, *gc;
    cudaGetSymbolAddress((void**)&hidden, g_hidden);
    cudaGetSymbolAddress((void**)&proj,   g_proj);
    cudaGetSymbolAddress((void**)&x4,     g_x4);
    cudaGetSymbolAddress((void**)&s1,     g_s1);
    cudaGetSymbolAddress((void**)&sn,     g_sn);
    cudaGetSymbolAddress((void**)&se,     g_se);
    cudaGetSymbolAddress((void**)&atte,   g_atte);
    cudaGetSymbolAddress((void**)&HTt,    g_HTt);
    cudaGetSymbolAddress((void**)&edge,   g_edge);
    cudaGetSymbolAddress((void**)&e4,     g_e4);
    cudaGetSymbolAddress((void**)&attn,   g_attn);
    cudaGetSymbolAddress((void**)&x1,     g_x1);
    cudaGetSymbolAddress((void**)&xW,     g_xW);
    cudaGetSymbolAddress((void**)&sem,    g_sem);
    cudaGetSymbolAddress((void**)&comb,   g_comb);
    cudaGetSymbolAddress((void**)&hpre,   g_hpre);
    cudaGetSymbolAddress((void**)&gc,     g_c);

    auto grid1 = [](int M, int N) { return dim3((N + 63) / 64, (M + 63) / 64, 1); };

    // scalars c1 = wc1.a11[:300], c2 = wc2.a12[:300]
    dot_scalar_k<<<1, 128>>>(wc1, a11, gc + 0, Ff);
    dot_scalar_k<<<1, 128>>>(wc2, a12, gc + 1, HH);

    gather_k<<<ROWS, 128>>>(inp, emb, hidden);
    transpose_k<<<dim3(Nn / 32, Ee / 32, Bb), dim3(32, 8)>>>(HT, HTt);

    // proj = hidden @ Wp^T + bp
    sgemm_k<true, 0><<<grid1(ROWS, HH), 256>>>(hidden, Wp, bp, proj, ROWS, HH, Ff, 0, 0, 0);

    // ---- layer 1 (alpha=0.1, concat=True, no transfer) ----
    sgemm_k<false, 0><<<grid1(ROWS, Ff), 256>>>(hidden, w2_1, nullptr, x4, ROWS, Ff, Ff, 0, 0, 0);
    rowdots_k<<<ROWS, 128>>>(x4, a11 + Ff, a21, gc + 0, 0.1f, s1, sn, Ff);
    softmax_edge_k<<<dim3(Ee, Bb), 256>>>(HT, s1, atte);
    // edge = att_e @ hidden   (batched: M=512, K=1024, N=300)
    sgemm_k<false, 0><<<dim3((Ff + 63) / 64, (Ee + 63) / 64, Bb), 256>>>(
        atte, hidden, nullptr, edge, Ee, Ff, Nn,
        (long)Ee * Nn, (long)Nn * Ff, (long)Ee * Ff);
    sgemm_k<false, 0><<<grid1(EROWS, Ff), 256>>>(edge, w3_1, nullptr, e4, EROWS, Ff, Ff, 0, 0, 0);
    rowdot_k<<<EROWS, 128>>>(e4, a21 + Ff, se, Ff);
    softmax_node_k<<<dim3(Nn, Bb), 256>>>(HTt, sn, se, 0.1f, attn);
    // x1 = elu(att_n @ edge)  (batched: M=1024, K=512, N=300)
    sgemm_k<false, 1><<<dim3((Ff + 63) / 64, (Nn + 63) / 64, Bb), 256>>>(
        attn, edge, nullptr, x1, Nn, Ff, Ee,
        (long)Nn * Ee, (long)Ee * Ff, (long)Nn * Ff);

    // ---- layer 2 (alpha=0.2, concat=False, transfer W2t) ----
    sgemm_k<false, 0><<<grid1(ROWS, HH), 256>>>(x1, w2_2, nullptr, x4, ROWS, HH, Ff, 0, 0, 0);
    sgemm_k<false, 0><<<grid1(ROWS, HH), 256>>>(x1, W2t, nullptr, xW, ROWS, HH, Ff, 0, 0, 0);
    rowdots_k<<<ROWS, 128>>>(x4, a12 + HH, a22, gc + 1, 0.2f, s1, sn, HH);
    softmax_edge_k<<<dim3(Ee, Bb), 256>>>(HT, s1, atte);
    sgemm_k<false, 0><<<dim3((HH + 63) / 64, (Ee + 63) / 64, Bb), 256>>>(
        atte, xW, nullptr, edge, Ee, HH, Nn,
        (long)Ee * Nn, (long)Nn * HH, (long)Ee * HH);
    sgemm_k<false, 0><<<grid1(EROWS, HH), 256>>>(edge, w3_2, nullptr, e4, EROWS, HH, HH, 0, 0, 0);
    rowdot_k<<<EROWS, 128>>>(e4, a22 + HH, se, HH);
    softmax_node_k<<<dim3(Nn, Bb), 256>>>(HTt, sn, se, 0.2f, attn);
    // sem = att_n @ edge  (no activation)
    sgemm_k<false, 0><<<dim3((HH + 63) / 64, (Nn + 63) / 64, Bb), 256>>>(
        attn, edge, nullptr, sem, Nn, HH, Ee,
        (long)Nn * Ee, (long)Ee * HH, (long)Nn * HH);

    // ---- head: comb -> tanh -> LN -> gate -> mix ----
    concat_k<<<ROWS, 128>>>(proj, sem, comb);
    sgemm_k<true, 0><<<grid1(ROWS, HH), 256>>>(comb, A1, b1, hpre, ROWS, HH, 2 * HH, 0, 0, 0);
    final_k<<<ROWS, 128>>>(hpre, proj, sem, ln_g, ln_b, A2, b2, outp);
}

// round 4
// speedup vs baseline: 2.7926x; 2.7926x over previous
#include <cuda_runtime.h>
#include <math.h>

#define Bb 32
#define Nn 1024
#define Ee 512
#define Ff 300
#define HH 300
#define Vv 50001
#define NEGV (-9.0e15f)

constexpr int ROWS  = Bb * Nn;   // 32768
constexpr int EROWS = Bb * Ee;   // 16384

// ---------------- scratch ----------------------------------------------------
__device__ float g_hidden[ROWS * Ff];
__device__ float g_proj  [ROWS * HH];
__device__ float g_x4    [ROWS * Ff];
__device__ float g_s1    [ROWS];
__device__ float g_sn    [ROWS];
__device__ float g_se    [EROWS];
__device__ float g_atte  [Bb * Ee * Nn];
__device__ float g_HTt   [Bb * Nn * Ee];
__device__ float g_edge  [EROWS * Ff];
__device__ float g_e4    [EROWS * Ff];
__device__ float g_attn  [Bb * Nn * Ee];
__device__ float g_x1    [ROWS * Ff];
__device__ float g_xW    [ROWS * HH];
__device__ float g_sem   [ROWS * HH];
__device__ float g_comb  [ROWS * 2 * HH];
__device__ float g_hpre  [ROWS * HH];
__device__ float g_c     [2];

// ---------------- tf32 helpers ----------------------------------------------
__device__ __forceinline__ unsigned to_tf32(float x) {
    unsigned r;
    asm("cvt.rna.tf32.f32 %0, %1;" : "=r"(r) : "f"(x));
    return r;
}

__device__ __forceinline__ void mma_tf32(float* d, const unsigned* a, const unsigned* b) {
    asm volatile(
        "mma.sync.aligned.m16n8k8.row.col.f32.tf32.tf32.f32 "
        "{%0,%1,%2,%3}, {%4,%5,%6,%7}, {%8,%9}, {%0,%1,%2,%3};"
        : "+f"(d[0]), "+f"(d[1]), "+f"(d[2]), "+f"(d[3])
        : "r"(a[0]), "r"(a[1]), "r"(a[2]), "r"(a[3]), "r"(b[0]), "r"(b[1]));
}

// ---------------- tensor-core GEMM: C = A @ B (opt B^T), opt bias/ELU -------
// A: [M,K] row-major. B: [K,N] (TRANSB=false) or [N,K] (TRANSB=true).
// Requires K % 4 == 0, N % 2 == 0 (all shapes here satisfy this).
// Block tile 128x64, BK=32, 256 threads, warp grid 4x2 (warp tile 32x32).
template <bool TRANSB, int ACT>
__global__ void __launch_bounds__(256)
mma_gemm_k(const float* __restrict__ A, const float* __restrict__ B,
           const float* __restrict__ bias, float* __restrict__ C,
           int M, int N, int K, long sA, long sB, long sC)
{
    A += (long)blockIdx.z * sA;
    B += (long)blockIdx.z * sB;
    C += (long)blockIdx.z * sC;

    const int tid  = threadIdx.x;
    const int warp = tid >> 5, lane = tid & 31;
    const int g    = lane >> 2, tig = lane & 3;
    const int wm   = warp >> 1, wn = warp & 1;
    const int m0   = blockIdx.y * 128, n0 = blockIdx.x * 64;

    __shared__ __align__(16) float As[128][36];   // [m][k], pad->stride 36
    __shared__ __align__(16) float Bs[32][72];    // [k][n], pad->stride 72

    float acc[2][4][4];
#pragma unroll
    for (int i = 0; i < 2; ++i)
#pragma unroll
        for (int j = 0; j < 4; ++j)
#pragma unroll
            for (int l = 0; l < 4; ++l) acc[i][j][l] = 0.f;

    const int kt = (K + 31) / 32;
    float4 apf[4], bpf[2];

    auto loadA = [&](int k0) {
#pragma unroll
        for (int t = 0; t < 4; ++t) {
            int f = tid + t * 256;
            int row = f >> 3, c4 = (f & 7) * 4;
            int gm = m0 + row, gk = k0 + c4;
            float4 v = make_float4(0.f, 0.f, 0.f, 0.f);
            if (gm < M && gk < K) v = *(const float4*)(A + (long)gm * K + gk);
            apf[t] = v;
        }
    };
    auto storeA = [&]() {
#pragma unroll
        for (int t = 0; t < 4; ++t) {
            int f = tid + t * 256;
            int row = f >> 3, c4 = (f & 7) * 4;
            float4 v = apf[t];
            v.x = __uint_as_float(to_tf32(v.x));
            v.y = __uint_as_float(to_tf32(v.y));
            v.z = __uint_as_float(to_tf32(v.z));
            v.w = __uint_as_float(to_tf32(v.w));
            *(float4*)&As[row][c4] = v;
        }
    };
    auto loadB = [&](int k0) {
#pragma unroll
        for (int t = 0; t < 2; ++t) {
            int f = tid + t * 256;
            float4 v = make_float4(0.f, 0.f, 0.f, 0.f);
            if (TRANSB) {
                int nr = f >> 3, k4 = (f & 7) * 4;
                int gn = n0 + nr, gk = k0 + k4;
                if (gn < N && gk < K) v = *(const float4*)(B + (long)gn * K + gk);
            } else {
                int row = f >> 4, c4 = (f & 15) * 4;
                int gk = k0 + row, gn = n0 + c4;
                if (gk < K && gn < N) v = *(const float4*)(B + (long)gk * N + gn);
            }
            bpf[t] = v;
        }
    };
    auto storeB = [&]() {
#pragma unroll
        for (int t = 0; t < 2; ++t) {
            int f = tid + t * 256;
            float4 v = bpf[t];
            if (TRANSB) {
                int nr = f >> 3, k4 = (f & 7) * 4;
                Bs[k4 + 0][nr] = __uint_as_float(to_tf32(v.x));
                Bs[k4 + 1][nr] = __uint_as_float(to_tf32(v.y));
                Bs[k4 + 2][nr] = __uint_as_float(to_tf32(v.z));
                Bs[k4 + 3][nr] = __uint_as_float(to_tf32(v.w));
            } else {
                int row = f >> 4, c4 = (f & 15) * 4;
                v.x = __uint_as_float(to_tf32(v.x));
                v.y = __uint_as_float(to_tf32(v.y));
                v.z = __uint_as_float(to_tf32(v.z));
                v.w = __uint_as_float(to_tf32(v.w));
                *(float4*)&Bs[row][c4] = v;
            }
        }
    };

    loadA(0); loadB(0);
    storeA(); storeB();
    __syncthreads();

    for (int t = 0; t < kt; ++t) {
        if (t + 1 < kt) { loadA((t + 1) * 32); loadB((t + 1) * 32); }

#pragma unroll
        for (int ks = 0; ks < 4; ++ks) {
            const int kb = ks * 8;
            unsigned af[2][4], bf[4][2];
#pragma unroll
            for (int mi = 0; mi < 2; ++mi) {
                int r = wm * 32 + mi * 16 + g;
                af[mi][0] = __float_as_uint(As[r    ][kb + tig]);
                af[mi][1] = __float_as_uint(As[r + 8][kb + tig]);
                af[mi][2] = __float_as_uint(As[r    ][kb + tig + 4]);
                af[mi][3] = __float_as_uint(As[r + 8][kb + tig + 4]);
            }
#pragma unroll
            for (int ni = 0; ni < 4; ++ni) {
                int c = wn * 32 + ni * 8 + g;
                bf[ni][0] = __float_as_uint(Bs[kb + tig    ][c]);
                bf[ni][1] = __float_as_uint(Bs[kb + tig + 4][c]);
            }
#pragma unroll
            for (int mi = 0; mi < 2; ++mi)
#pragma unroll
                for (int ni = 0; ni < 4; ++ni)
                    mma_tf32(acc[mi][ni], af[mi], bf[ni]);
        }

        __syncthreads();
        if (t + 1 < kt) {
            storeA(); storeB();
            __syncthreads();
        }
    }

    // epilogue: d0=(g,2t) d1=(g,2t+1) d2=(g+8,2t) d3=(g+8,2t+1)
#pragma unroll
    for (int mi = 0; mi < 2; ++mi) {
#pragma unroll
        for (int ni = 0; ni < 4; ++ni) {
            int r = m0 + wm * 32 + mi * 16 + g;
            int c = n0 + wn * 32 + ni * 8 + tig * 2;
            if (c >= N) continue;
            float bx = bias ? bias[c] : 0.f;
            float by = bias ? bias[c + 1] : 0.f;
#pragma unroll
            for (int h = 0; h < 2; ++h) {
                int rr = r + h * 8;
                if (rr >= M) continue;
                float vx = acc[mi][ni][h * 2 + 0] + bx;
                float vy = acc[mi][ni][h * 2 + 1] + by;
                if (ACT == 1) {
                    vx = (vx > 0.f) ? vx : expm1f(vx);
                    vy = (vy > 0.f) ? vy : expm1f(vy);
                }
                float2 o = make_float2(vx, vy);
                *(float2*)(C + (long)rr * N + c) = o;
            }
        }
    }
}

// ---------------- small kernels ---------------------------------------------
__global__ void gather_k(const int* __restrict__ idx,
                         const float* __restrict__ emb, float* __restrict__ out)
{
    int row = blockIdx.x;
    int id = idx[row];
    id = max(0, min(id, Vv - 1));
    const float* src = emb + (long)id * Ff;
    float* dst = out + (long)row * Ff;
    for (int c = threadIdx.x; c < Ff; c += blockDim.x) dst[c] = src[c];
}

__global__ void dot_scalar_k(const float* __restrict__ a, const float* __restrict__ b,
                             float* __restrict__ out, int K)
{
    __shared__ float sh[128];
    float s = 0.f;
    for (int c = threadIdx.x; c < K; c += 128) s += a[c] * b[c];
    sh[threadIdx.x] = s; __syncthreads();
    for (int o = 64; o > 0; o >>= 1) {
        if (threadIdx.x < o) sh[threadIdx.x] += sh[threadIdx.x + o];
        __syncthreads();
    }
    if (threadIdx.x == 0) *out = sh[0];
}

__global__ void rowdots_k(const float* __restrict__ X, const float* __restrict__ v1,
                          const float* __restrict__ v2, const float* __restrict__ cptr,
                          float alpha, float* __restrict__ o1, float* __restrict__ o2, int K)
{
    int row = blockIdx.x;
    const float* x = X + (long)row * K;
    float s1 = 0.f, s2 = 0.f;
    for (int c = threadIdx.x; c < K; c += 128) {
        float xv = x[c];
        s1 += xv * v1[c];
        s2 += xv * v2[c];
    }
    __shared__ float r1[128], r2[128];
    r1[threadIdx.x] = s1; r2[threadIdx.x] = s2; __syncthreads();
    for (int o = 64; o > 0; o >>= 1) {
        if (threadIdx.x < o) { r1[threadIdx.x] += r1[threadIdx.x + o]; r2[threadIdx.x] += r2[threadIdx.x + o]; }
        __syncthreads();
    }
    if (threadIdx.x == 0) {
        float t = *cptr + r1[0];
        o1[row] = (t >= 0.f) ? t : alpha * t;
        o2[row] = r2[0];
    }
}

__global__ void rowdot_k(const float* __restrict__ X, const float* __restrict__ v,
                         float* __restrict__ o, int K)
{
    int row = blockIdx.x;
    const float* x = X + (long)row * K;
    float s = 0.f;
    for (int c = threadIdx.x; c < K; c += 128) s += x[c] * v[c];
    __shared__ float sh[128];
    sh[threadIdx.x] = s; __syncthreads();
    for (int o2 = 64; o2 > 0; o2 >>= 1) {
        if (threadIdx.x < o2) sh[threadIdx.x] += sh[threadIdx.x + o2];
        __syncthreads();
    }
    if (threadIdx.x == 0) o[row] = sh[0];
}

__global__ void softmax_edge_k(const float* __restrict__ HT, const float* __restrict__ s1,
                               float* __restrict__ att)
{
    int b = blockIdx.y, e = blockIdx.x;
    const float* ht = HT + ((long)b * Ee + e) * Nn;
    const float* s  = s1 + (long)b * Nn;
    __shared__ float sv[Nn];
    __shared__ float red[256];
    int tid = threadIdx.x;

    float mx = -3.0e38f;
    for (int n = tid; n < Nn; n += 256) {
        float v = (ht[n] > 0.f) ? s[n] : NEGV;
        sv[n] = v;
        mx = fmaxf(mx, v);
    }
    red[tid] = mx; __syncthreads();
    for (int o = 128; o > 0; o >>= 1) {
        if (tid < o) red[tid] = fmaxf(red[tid], red[tid + o]);
        __syncthreads();
    }
    mx = red[0]; __syncthreads();

    float sum = 0.f;
    for (int n = tid; n < Nn; n += 256) {
        float ev = expf(sv[n] - mx);
        sv[n] = ev;
        sum += ev;
    }
    red[tid] = sum; __syncthreads();
    for (int o = 128; o > 0; o >>= 1) {
        if (tid < o) red[tid] += red[tid + o];
        __syncthreads();
    }
    float inv = 1.f / red[0];
    float* arow = att + ((long)b * Ee + e) * Nn;
    for (int n = tid; n < Nn; n += 256) arow[n] = sv[n] * inv;
}

__global__ void softmax_node_k(const float* __restrict__ HTt, const float* __restrict__ sn,
                               const float* __restrict__ se, float alpha,
                               float* __restrict__ att)
{
    int b = blockIdx.y, n = blockIdx.x;
    const float* ht  = HTt + ((long)b * Nn + n) * Ee;
    const float* seb = se + (long)b * Ee;
    float snv = sn[(long)b * Nn + n];
    __shared__ float sv[Ee];
    __shared__ float red[256];
    int tid = threadIdx.x;

    float mx = -3.0e38f;
    for (int e = tid; e < Ee; e += 256) {
        float t = snv + seb[e];
        t = (t >= 0.f) ? t : alpha * t;
        float v = (ht[e] > 0.f) ? t : NEGV;
        sv[e] = v;
        mx = fmaxf(mx, v);
    }
    red[tid] = mx; __syncthreads();
    for (int o = 128; o > 0; o >>= 1) {
        if (tid < o) red[tid] = fmaxf(red[tid], red[tid + o]);
        __syncthreads();
    }
    mx = red[0]; __syncthreads();

    float sum = 0.f;
    for (int e = tid; e < Ee; e += 256) {
        float ev = expf(sv[e] - mx);
        sv[e] = ev;
        sum += ev;
    }
    red[tid] = sum; __syncthreads();
    for (int o = 128; o > 0; o >>= 1) {
        if (tid < o) red[tid] += red[tid + o];
        __syncthreads();
    }
    float inv = 1.f / red[0];
    float* arow = att + ((long)b * Nn + n) * Ee;
    for (int e = tid; e < Ee; e += 256) arow[e] = sv[e] * inv;
}

__global__ void transpose_k(const float* __restrict__ HT, float* __restrict__ HTt)
{
    __shared__ float t[32][33];
    int b  = blockIdx.z;
    int n0 = blockIdx.x * 32, e0 = blockIdx.y * 32;
    const float* src = HT + (long)b * Ee * Nn;
    float* dst = HTt + (long)b * Nn * Ee;
    int tx = threadIdx.x, ty = threadIdx.y;
#pragma unroll
    for (int i = 0; i < 32; i += 8)
        t[ty + i][tx] = src[(long)(e0 + ty + i) * Nn + n0 + tx];
    __syncthreads();
#pragma unroll
    for (int i = 0; i < 32; i += 8)
        dst[(long)(n0 + ty + i) * Ee + e0 + tx] = t[tx][ty + i];
}

__global__ void concat_k(const float* __restrict__ proj, const float* __restrict__ sem,
                         float* __restrict__ comb)
{
    int row = blockIdx.x;
    float* dst = comb + (long)row * (2 * HH);
    const float* p = proj + (long)row * HH;
    const float* s = sem + (long)row * HH;
    for (int c = threadIdx.x; c < HH; c += 128) {
        dst[c]      = p[c];
        dst[HH + c] = s[c];
    }
}

__global__ void final_k(const float* __restrict__ hpre, const float* __restrict__ proj,
                        const float* __restrict__ sem, const float* __restrict__ ln_g,
                        const float* __restrict__ ln_b, const float* __restrict__ A2,
                        const float* __restrict__ b2, float* __restrict__ out)
{
    int row = blockIdx.x;
    int tid = threadIdx.x;
    __shared__ float hs[HH];
    __shared__ float red[128];
    const float* hp = hpre + (long)row * HH;

    float s = 0.f;
    for (int c = tid; c < HH; c += 128) {
        float t = tanhf(hp[c]);
        hs[c] = t;
        s += t;
    }
    red[tid] = s; __syncthreads();
    for (int o = 64; o > 0; o >>= 1) {
        if (tid < o) red[tid] += red[tid + o];
        __syncthreads();
    }
    float mean = red[0] / (float)HH;
    __syncthreads();

    float vs = 0.f;
    for (int c = tid; c < HH; c += 128) { float d = hs[c] - mean; vs += d * d; }
    red[tid] = vs; __syncthreads();
    for (int o = 64; o > 0; o >>= 1) {
        if (tid < o) red[tid] += red[tid + o];
        __syncthreads();
    }
    float rstd = rsqrtf(red[0] / (float)HH + 1e-5f);
    __syncthreads();

    float gdot = 0.f;
    for (int c = tid; c < HH; c += 128) {
        float hn = (hs[c] - mean) * rstd * ln_g[c] + ln_b[c];
        gdot += hn * A2[c];
    }
    red[tid] = gdot; __syncthreads();
    for (int o = 64; o > 0; o >>= 1) {
        if (tid < o) red[tid] += red[tid + o];
        __syncthreads();
    }
    float gate = 1.f / (1.f + expf(-(red[0] + b2[0])));
    __syncthreads();

    const float* p = proj + (long)row * HH;
    const float* se = sem + (long)row * HH;
    float* o = out + (long)row * HH;
    for (int c = tid; c < HH; c += 128)
        o[c] = gate * se[c] + (1.f - gate) * p[c];
}

// ---------------- launcher ---------------------------------------------------
extern "C" void kernel_launch(void* const* d_in, const int* in_sizes, int n_in,
                              void* d_out, int out_size)
{
    const int*   inp  = (const int*)d_in[0];
    const float* HT   = (const float*)d_in[1];
    const float* emb  = (const float*)d_in[2];
    const float* Wp   = (const float*)d_in[3];
    const float* bp   = (const float*)d_in[4];
    const float* w2_1 = (const float*)d_in[5];
    const float* w3_1 = (const float*)d_in[6];
    const float* wc1  = (const float*)d_in[7];
    const float* a11  = (const float*)d_in[8];
    const float* a21  = (const float*)d_in[9];
    const float* W2t  = (const float*)d_in[10];
    const float* w2_2 = (const float*)d_in[11];
    const float* w3_2 = (const float*)d_in[12];
    const float* wc2  = (const float*)d_in[13];
    const float* a12  = (const float*)d_in[14];
    const float* a22  = (const float*)d_in[15];
    const float* A1   = (const float*)d_in[16];
    const float* b1   = (const float*)d_in[17];
    const float* ln_g = (const float*)d_in[18];
    const float* ln_b = (const float*)d_in[19];
    const float* A2   = (const float*)d_in[20];
    const float* b2   = (const float*)d_in[21];
    float* outp = (float*)d_out;

    float *hidden, *proj, *x4, *s1, *sn, *se, *atte, *HTt, *edge, *e4, *attn,
          *x1, *xW, *sem, *comb, *hpre, *gc;
    cudaGetSymbolAddress((void**)&hidden, g_hidden);
    cudaGetSymbolAddress((void**)&proj,   g_proj);
    cudaGetSymbolAddress((void**)&x4,     g_x4);
    cudaGetSymbolAddress((void**)&s1,     g_s1);
    cudaGetSymbolAddress((void**)&sn,     g_sn);
    cudaGetSymbolAddress((void**)&se,     g_se);
    cudaGetSymbolAddress((void**)&atte,   g_atte);
    cudaGetSymbolAddress((void**)&HTt,    g_HTt);
    cudaGetSymbolAddress((void**)&edge,   g_edge);
    cudaGetSymbolAddress((void**)&e4,     g_e4);
    cudaGetSymbolAddress((void**)&attn,   g_attn);
    cudaGetSymbolAddress((void**)&x1,     g_x1);
    cudaGetSymbolAddress((void**)&xW,     g_xW);
    cudaGetSymbolAddress((void**)&sem,    g_sem);
    cudaGetSymbolAddress((void**)&comb,   g_comb);
    cudaGetSymbolAddress((void**)&hpre,   g_hpre);
    cudaGetSymbolAddress((void**)&gc,     g_c);

    auto grid = [](int M, int N, int Z) {
        return dim3((N + 63) / 64, (M + 127) / 128, Z);
    };

    dot_scalar_k<<<1, 128>>>(wc1, a11, gc + 0, Ff);
    dot_scalar_k<<<1, 128>>>(wc2, a12, gc + 1, HH);

    gather_k<<<ROWS, 128>>>(inp, emb, hidden);
    transpose_k<<<dim3(Nn / 32, Ee / 32, Bb), dim3(32, 8)>>>(HT, HTt);

    // proj = hidden @ Wp^T + bp
    mma_gemm_k<true, 0><<<grid(ROWS, HH, 1), 256>>>(hidden, Wp, bp, proj, ROWS, HH, Ff, 0, 0, 0);

    // ---- layer 1 ----
    mma_gemm_k<false, 0><<<grid(ROWS, Ff, 1), 256>>>(hidden, w2_1, nullptr, x4, ROWS, Ff, Ff, 0, 0, 0);
    rowdots_k<<<ROWS, 128>>>(x4, a11 + Ff, a21, gc + 0, 0.1f, s1, sn, Ff);
    softmax_edge_k<<<dim3(Ee, Bb), 256>>>(HT, s1, atte);
    mma_gemm_k<false, 0><<<grid(Ee, Ff, Bb), 256>>>(
        atte, hidden, nullptr, edge, Ee, Ff, Nn,
        (long)Ee * Nn, (long)Nn * Ff, (long)Ee * Ff);
    mma_gemm_k<false, 0><<<grid(EROWS, Ff, 1), 256>>>(edge, w3_1, nullptr, e4, EROWS, Ff, Ff, 0, 0, 0);
    rowdot_k<<<EROWS, 128>>>(e4, a21 + Ff, se, Ff);
    softmax_node_k<<<dim3(Nn, Bb), 256>>>(HTt, sn, se, 0.1f, attn);
    mma_gemm_k<false, 1><<<grid(Nn, Ff, Bb), 256>>>(
        attn, edge, nullptr, x1, Nn, Ff, Ee,
        (long)Nn * Ee, (long)Ee * Ff, (long)Nn * Ff);

    // ---- layer 2 ----
    mma_gemm_k<false, 0><<<grid(ROWS, HH, 1), 256>>>(x1, w2_2, nullptr, x4, ROWS, HH, Ff, 0, 0, 0);
    mma_gemm_k<false, 0><<<grid(ROWS, HH, 1), 256>>>(x1, W2t, nullptr, xW, ROWS, HH, Ff, 0, 0, 0);
    rowdots_k<<<ROWS, 128>>>(x4, a12 + HH, a22, gc + 1, 0.2f, s1, sn, HH);
    softmax_edge_k<<<dim3(Ee, Bb), 256>>>(HT, s1, atte);
    mma_gemm_k<false, 0><<<grid(Ee, HH, Bb), 256>>>(
        atte, xW, nullptr, edge, Ee, HH, Nn,
        (long)Ee * Nn, (long)Nn * HH, (long)Ee * HH);
    mma_gemm_k<false, 0><<<grid(EROWS, HH, 1), 256>>>(edge, w3_2, nullptr, e4, EROWS, HH, HH, 0, 0, 0);
    rowdot_k<<<EROWS, 128>>>(e4, a22 + HH, se, HH);
    softmax_node_k<<<dim3(Nn, Bb), 256>>>(HTt, sn, se, 0.2f, attn);
    mma_gemm_k<false, 0><<<grid(Nn, HH, Bb), 256>>>(
        attn, edge, nullptr, sem, Nn, HH, Ee,
        (long)Nn * Ee, (long)Ee * HH, (long)Nn * HH);

    // ---- head ----
    concat_k<<<ROWS, 128>>>(proj, sem, comb);
    mma_gemm_k<true, 0><<<grid(ROWS, HH, 1), 256>>>(comb, A1, b1, hpre, ROWS, HH, 2 * HH, 0, 0, 0);
    final_k<<<ROWS, 128>>>(hpre, proj, sem, ln_g, ln_b, A2, b2, outp);
}

// round 5
// speedup vs baseline: 3.1967x; 1.1447x over previous
#include <cuda_runtime.h>
#include <math.h>

#define Bb 32
#define Nn 1024
#define Ee 512
#define Ff 300
#define HH 300
#define Vv 50001

constexpr int ROWS  = Bb * Nn;   // 32768
constexpr int EROWS = Bb * Ee;   // 16384
constexpr int YW    = 304;       // y/edge row width (300 data + w/Z + pad)
constexpr int SMEMB = (128 * 36 + 32 * 72) * 2 * 4;   // 55296 B, 2 stages

// ---------------- scratch ----------------------------------------------------
__device__ float g_hidden[ROWS * Ff];
__device__ float g_proj  [ROWS * HH];
__device__ float g_x4    [ROWS * Ff];
__device__ float g_s1    [ROWS];
__device__ float g_sn    [ROWS];
__device__ float g_se    [EROWS];
__device__ float g_y     [ROWS * YW];
__device__ float g_edge  [EROWS * YW];
__device__ float g_e4    [EROWS * Ff];
__device__ float g_u2    [Bb * Nn * Ee];
__device__ float g_zpart [ROWS * 16];
__device__ float g_invZe [EROWS];
__device__ float g_invZn [ROWS];
__device__ float g_x1    [ROWS * Ff];
__device__ float g_xW    [ROWS * HH];
__device__ float g_sem   [ROWS * HH];
__device__ float g_comb  [ROWS * 2 * HH];
__device__ float g_hpre  [ROWS * HH];
__device__ float g_c     [2];
__device__ float g_s1max [Bb];
__device__ float g_snmax [Bb];
__device__ float g_semax [Bb];

// ---------------- tf32 helpers ----------------------------------------------
__device__ __forceinline__ unsigned to_tf32(float x) {
    unsigned r;
    asm("cvt.rna.tf32.f32 %0, %1;" : "=r"(r) : "f"(x));
    return r;
}

__device__ __forceinline__ void mma_tf32(float* d, const unsigned* a, const unsigned* b) {
    asm volatile(
        "mma.sync.aligned.m16n8k8.row.col.f32.tf32.tf32.f32 "
        "{%0,%1,%2,%3}, {%4,%5,%6,%7}, {%8,%9}, {%0,%1,%2,%3};"
        : "+f"(d[0]), "+f"(d[1]), "+f"(d[2]), "+f"(d[3])
        : "r"(a[0]), "r"(a[1]), "r"(a[2]), "r"(a[3]), "r"(b[0]), "r"(b[1]));
}

// ---------------- tensor-core GEMM, 2-stage double buffer -------------------
// C = rowscale(A @ B) (+bias) (ELU).  A:[M,K] lda. B: [K,N] ldb (or [N,K] if TRANSB).
// Block tile 128x64, BK=32, 256 threads, warp grid 4x2 (warp tile 32x32).
template <bool TRANSB, int ACT>
__global__ void __launch_bounds__(256)
mma_gemm_k(const float* __restrict__ A, const float* __restrict__ B,
           const float* __restrict__ bias, const float* __restrict__ rowscale,
           float* __restrict__ C,
           int M, int N, int K, int lda, int ldb, int ldc,
           long sA, long sB, long sC, long sScale)
{
    extern __shared__ float sm[];
    constexpr int SSTG = 128 * 36 + 32 * 72;   // floats per stage
    constexpr int BOFF = 128 * 36;

    A += (long)blockIdx.z * sA;
    B += (long)blockIdx.z * sB;
    C += (long)blockIdx.z * sC;
    const float* rs = rowscale ? rowscale + (long)blockIdx.z * sScale : nullptr;

    const int tid  = threadIdx.x;
    const int warp = tid >> 5, lane = tid & 31;
    const int g    = lane >> 2, tig = lane & 3;
    const int wm   = warp >> 1, wn = warp & 1;
    const int m0   = blockIdx.y * 128, n0 = blockIdx.x * 64;

    float acc[2][4][4];
#pragma unroll
    for (int i = 0; i < 2; ++i)
#pragma unroll
        for (int j = 0; j < 4; ++j)
#pragma unroll
            for (int l = 0; l < 4; ++l) acc[i][j][l] = 0.f;

    const int kt = (K + 31) / 32;
    float4 apf[4], bpf[2];

    auto loadA = [&](int k0) {
#pragma unroll
        for (int t = 0; t < 4; ++t) {
            int f = tid + t * 256;
            int row = f >> 3, c4 = (f & 7) * 4;
            int gm = m0 + row, gk = k0 + c4;
            float4 v = make_float4(0.f, 0.f, 0.f, 0.f);
            if (gm < M && gk < K) v = *(const float4*)(A + (long)gm * lda + gk);
            apf[t] = v;
        }
    };
    auto storeA = [&](int st) {
        float* As = sm + st * SSTG;
#pragma unroll
        for (int t = 0; t < 4; ++t) {
            int f = tid + t * 256;
            int row = f >> 3, c4 = (f & 7) * 4;
            float4 v = apf[t];
            v.x = __uint_as_float(to_tf32(v.x));
            v.y = __uint_as_float(to_tf32(v.y));
            v.z = __uint_as_float(to_tf32(v.z));
            v.w = __uint_as_float(to_tf32(v.w));
            *(float4*)&As[row * 36 + c4] = v;
        }
    };
    auto loadB = [&](int k0) {
#pragma unroll
        for (int t = 0; t < 2; ++t) {
            int f = tid + t * 256;
            float4 v = make_float4(0.f, 0.f, 0.f, 0.f);
            if (TRANSB) {
                int nr = f >> 3, k4 = (f & 7) * 4;
                int gn = n0 + nr, gk = k0 + k4;
                if (gn < N && gk < K) v = *(const float4*)(B + (long)gn * ldb + gk);
            } else {
                int row = f >> 4, c4 = (f & 15) * 4;
                int gk = k0 + row, gn = n0 + c4;
                if (gk < K && gn < N) v = *(const float4*)(B + (long)gk * ldb + gn);
            }
            bpf[t] = v;
        }
    };
    auto storeB = [&](int st) {
        float* Bs = sm + st * SSTG + BOFF;
#pragma unroll
        for (int t = 0; t < 2; ++t) {
            int f = tid + t * 256;
            float4 v = bpf[t];
            if (TRANSB) {
                int nr = f >> 3, k4 = (f & 7) * 4;
                Bs[(k4 + 0) * 72 + nr] = __uint_as_float(to_tf32(v.x));
                Bs[(k4 + 1) * 72 + nr] = __uint_as_float(to_tf32(v.y));
                Bs[(k4 + 2) * 72 + nr] = __uint_as_float(to_tf32(v.z));
                Bs[(k4 + 3) * 72 + nr] = __uint_as_float(to_tf32(v.w));
            } else {
                int row = f >> 4, c4 = (f & 15) * 4;
                v.x = __uint_as_float(to_tf32(v.x));
                v.y = __uint_as_float(to_tf32(v.y));
                v.z = __uint_as_float(to_tf32(v.z));
                v.w = __uint_as_float(to_tf32(v.w));
                *(float4*)&Bs[row * 72 + c4] = v;
            }
        }
    };

    loadA(0); loadB(0);
    storeA(0); storeB(0);
    __syncthreads();

    for (int t = 0; t < kt; ++t) {
        const int cur = t & 1;
        if (t + 1 < kt) { loadA((t + 1) * 32); loadB((t + 1) * 32); }

        const float* As = sm + cur * SSTG;
        const float* Bs = As + BOFF;
#pragma unroll
        for (int ks = 0; ks < 4; ++ks) {
            const int kb = ks * 8;
            unsigned af[2][4], bf[4][2];
#pragma unroll
            for (int mi = 0; mi < 2; ++mi) {
                int r = wm * 32 + mi * 16 + g;
                af[mi][0] = __float_as_uint(As[(r    ) * 36 + kb + tig]);
                af[mi][1] = __float_as_uint(As[(r + 8) * 36 + kb + tig]);
                af[mi][2] = __float_as_uint(As[(r    ) * 36 + kb + tig + 4]);
                af[mi][3] = __float_as_uint(As[(r + 8) * 36 + kb + tig + 4]);
            }
#pragma unroll
            for (int ni = 0; ni < 4; ++ni) {
                int c = wn * 32 + ni * 8 + g;
                bf[ni][0] = __float_as_uint(Bs[(kb + tig    ) * 72 + c]);
                bf[ni][1] = __float_as_uint(Bs[(kb + tig + 4) * 72 + c]);
            }
#pragma unroll
            for (int mi = 0; mi < 2; ++mi)
#pragma unroll
                for (int ni = 0; ni < 4; ++ni)
                    mma_tf32(acc[mi][ni], af[mi], bf[ni]);
        }

        if (t + 1 < kt) { storeA(cur ^ 1); storeB(cur ^ 1); }
        __syncthreads();
    }

#pragma unroll
    for (int mi = 0; mi < 2; ++mi) {
#pragma unroll
        for (int ni = 0; ni < 4; ++ni) {
            int r = m0 + wm * 32 + mi * 16 + g;
            int c = n0 + wn * 32 + ni * 8 + tig * 2;
            if (c >= N) continue;
            float bx = bias ? bias[c] : 0.f;
            float by = bias ? bias[c + 1] : 0.f;
#pragma unroll
            for (int h = 0; h < 2; ++h) {
                int rr = r + h * 8;
                if (rr >= M) continue;
                float sc = rs ? rs[rr] : 1.f;
                float vx = acc[mi][ni][h * 2 + 0] * sc + bx;
                float vy = acc[mi][ni][h * 2 + 1] * sc + by;
                if (ACT == 1) {
                    vx = (vx > 0.f) ? vx : expm1f(vx);
                    vy = (vy > 0.f) ? vy : expm1f(vy);
                }
                *(float2*)(C + (long)rr * ldc + c) = make_float2(vx, vy);
            }
        }
    }
}

// ---------------- small kernels ---------------------------------------------
__global__ void gather_k(const int* __restrict__ idx,
                         const float* __restrict__ emb, float* __restrict__ out)
{
    int row = blockIdx.x;
    int id = idx[row];
    id = max(0, min(id, Vv - 1));
    const float4* src = (const float4*)(emb + (long)id * Ff);
    float4* dst = (float4*)(out + (long)row * Ff);
    int c = threadIdx.x;
    if (c < Ff / 4) dst[c] = src[c];
}

__global__ void dot_scalar_k(const float* __restrict__ a, const float* __restrict__ b,
                             float* __restrict__ out, int K)
{
    __shared__ float sh[128];
    float s = 0.f;
    for (int c = threadIdx.x; c < K; c += 128) s += a[c] * b[c];
    sh[threadIdx.x] = s; __syncthreads();
    for (int o = 64; o > 0; o >>= 1) {
        if (threadIdx.x < o) sh[threadIdx.x] += sh[threadIdx.x + o];
        __syncthreads();
    }
    if (threadIdx.x == 0) *out = sh[0];
}

__global__ void rowdots_k(const float* __restrict__ X, const float* __restrict__ v1,
                          const float* __restrict__ v2, const float* __restrict__ cptr,
                          float alpha, float* __restrict__ o1, float* __restrict__ o2, int K)
{
    int row = blockIdx.x;
    const float* x = X + (long)row * K;
    float s1 = 0.f, s2 = 0.f;
    for (int c = threadIdx.x; c < K; c += 128) {
        float xv = x[c];
        s1 += xv * v1[c];
        s2 += xv * v2[c];
    }
    __shared__ float r1[128], r2[128];
    r1[threadIdx.x] = s1; r2[threadIdx.x] = s2; __syncthreads();
    for (int o = 64; o > 0; o >>= 1) {
        if (threadIdx.x < o) { r1[threadIdx.x] += r1[threadIdx.x + o]; r2[threadIdx.x] += r2[threadIdx.x + o]; }
        __syncthreads();
    }
    if (threadIdx.x == 0) {
        float t = *cptr + r1[0];
        o1[row] = (t >= 0.f) ? t : alpha * t;
        o2[row] = r2[0];
    }
}

__global__ void rowdot_k(const float* __restrict__ X, const float* __restrict__ v,
                         float* __restrict__ o, int K)
{
    int row = blockIdx.x;
    const float* x = X + (long)row * K;
    float s = 0.f;
    for (int c = threadIdx.x; c < K; c += 128) s += x[c] * v[c];
    __shared__ float sh[128];
    sh[threadIdx.x] = s; __syncthreads();
    for (int o2 = 64; o2 > 0; o2 >>= 1) {
        if (threadIdx.x < o2) sh[threadIdx.x] += sh[threadIdx.x + o2];
        __syncthreads();
    }
    if (threadIdx.x == 0) o[row] = sh[0];
}

// per-batch max over len entries
__global__ void bmax_k(const float* __restrict__ X, float* __restrict__ out, int len)
{
    __shared__ float sh[256];
    int b = blockIdx.x;
    const float* x = X + (long)b * len;
    float m = -3.0e38f;
    for (int i = threadIdx.x; i < len; i += 256) m = fmaxf(m, x[i]);
    sh[threadIdx.x] = m; __syncthreads();
    for (int o = 128; o > 0; o >>= 1) {
        if (threadIdx.x < o) sh[threadIdx.x] = fmaxf(sh[threadIdx.x], sh[threadIdx.x + o]);
        __syncthreads();
    }
    if (threadIdx.x == 0) out[b] = sh[0];
}

// y[row][0:300] = w*x[row], y[row][300] = w, y[row][301:304] = 0; w = exp(s1-max_b)
__global__ void build_y_k(const float* __restrict__ X, const float* __restrict__ s1,
                          const float* __restrict__ s1max, float* __restrict__ y)
{
    int row = blockIdx.x;
    int b = row >> 10;
    float w = expf(s1[row] - s1max[b]);
    const float* x = X + (long)row * Ff;
    float* yy = y + (long)row * YW;
    for (int c = threadIdx.x; c < YW; c += 128)
        yy[c] = (c < Ff) ? w * x[c] : ((c == Ff) ? w : 0.f);
}

__global__ void invze_k(const float* __restrict__ edge, float* __restrict__ invZe)
{
    int i = blockIdx.x * 256 + threadIdx.x;
    if (i < EROWS) {
        float z = edge[(long)i * YW + Ff];
        invZe[i] = (z > 0.f) ? 1.f / z : 0.f;
    }
}

// u2[b,n,e] = mask * exp(leaky(sn+se)-shift) * invZe[b,e]; zpart = per-tile row sums of u
__global__ void attn_build_k(const float* __restrict__ HT, const float* __restrict__ sn,
                             const float* __restrict__ se, const float* __restrict__ snmax,
                             const float* __restrict__ semax, const float* __restrict__ invZe,
                             float* __restrict__ u2, float* __restrict__ zpart, float alpha)
{
    __shared__ float t[32][33];
    int b  = blockIdx.z;
    int n0 = blockIdx.x * 32, e0 = blockIdx.y * 32;
    int tx = threadIdx.x, ty = threadIdx.y;   // (32,8)

    float sh = snmax[b] + semax[b];
    sh = (sh >= 0.f) ? sh : alpha * sh;       // leaky(upper bound) — valid shift

    const float* src = HT + (long)b * Ee * Nn;
    float snv = sn[(long)b * Nn + n0 + tx];
#pragma unroll
    for (int i = 0; i < 32; i += 8) {
        int e = e0 + ty + i;
        float sev = se[(long)b * Ee + e];
        float ht  = src[(long)e * Nn + n0 + tx];
        float v = snv + sev;
        v = (v >= 0.f) ? v : alpha * v;
        t[ty + i][tx] = (ht > 0.f) ? expf(v - sh) : 0.f;
    }
    __syncthreads();

    float iz = invZe[(long)b * Ee + e0 + tx];
    float* dst = u2 + (long)b * Nn * Ee;
#pragma unroll
    for (int i = 0; i < 32; i += 8) {
        int n = n0 + ty + i;
        dst[(long)n * Ee + e0 + tx] = t[tx][ty + i] * iz;
    }

    if (ty == 0) {
        float s = 0.f;
#pragma unroll
        for (int e = 0; e < 32; ++e) s += t[e][tx];
        zpart[((long)b * Nn + n0 + tx) * 16 + blockIdx.y] = s;
    }
}

__global__ void zsum_k(const float* __restrict__ zpart, float* __restrict__ invZn)
{
    int i = blockIdx.x * 256 + threadIdx.x;
    if (i < ROWS) {
        float s = 0.f;
#pragma unroll
        for (int j = 0; j < 16; ++j) s += zpart[(long)i * 16 + j];
        invZn[i] = (s > 0.f) ? 1.f / s : 0.f;
    }
}

__global__ void concat_k(const float* __restrict__ proj, const float* __restrict__ sem,
                         float* __restrict__ comb)
{
    int row = blockIdx.x;
    float* dst = comb + (long)row * (2 * HH);
    const float* p = proj + (long)row * HH;
    const float* s = sem + (long)row * HH;
    for (int c = threadIdx.x; c < HH; c += 128) {
        dst[c]      = p[c];
        dst[HH + c] = s[c];
    }
}

__global__ void final_k(const float* __restrict__ hpre, const float* __restrict__ proj,
                        const float* __restrict__ sem, const float* __restrict__ ln_g,
                        const float* __restrict__ ln_b, const float* __restrict__ A2,
                        const float* __restrict__ b2, float* __restrict__ out)
{
    int row = blockIdx.x;
    int tid = threadIdx.x;
    __shared__ float hs[HH];
    __shared__ float red[128];
    const float* hp = hpre + (long)row * HH;

    float s = 0.f;
    for (int c = tid; c < HH; c += 128) {
        float t = tanhf(hp[c]);
        hs[c] = t;
        s += t;
    }
    red[tid] = s; __syncthreads();
    for (int o = 64; o > 0; o >>= 1) {
        if (tid < o) red[tid] += red[tid + o];
        __syncthreads();
    }
    float mean = red[0] / (float)HH;
    __syncthreads();

    float vs = 0.f;
    for (int c = tid; c < HH; c += 128) { float d = hs[c] - mean; vs += d * d; }
    red[tid] = vs; __syncthreads();
    for (int o = 64; o > 0; o >>= 1) {
        if (tid < o) red[tid] += red[tid + o];
        __syncthreads();
    }
    float rstd = rsqrtf(red[0] / (float)HH + 1e-5f);
    __syncthreads();

    float gdot = 0.f;
    for (int c = tid; c < HH; c += 128) {
        float hn = (hs[c] - mean) * rstd * ln_g[c] + ln_b[c];
        gdot += hn * A2[c];
    }
    red[tid] = gdot; __syncthreads();
    for (int o = 64; o > 0; o >>= 1) {
        if (tid < o) red[tid] += red[tid + o];
        __syncthreads();
    }
    float gate = 1.f / (1.f + expf(-(red[0] + b2[0])));
    __syncthreads();

    const float* p = proj + (long)row * HH;
    const float* se = sem + (long)row * HH;
    float* o = out + (long)row * HH;
    for (int c = tid; c < HH; c += 128)
        o[c] = gate * se[c] + (1.f - gate) * p[c];
}

// ---------------- launcher ---------------------------------------------------
extern "C" void kernel_launch(void* const* d_in, const int* in_sizes, int n_in,
                              void* d_out, int out_size)
{
    const int*   inp  = (const int*)d_in[0];
    const float* HT   = (const float*)d_in[1];
    const float* emb  = (const float*)d_in[2];
    const float* Wp   = (const float*)d_in[3];
    const float* bp   = (const float*)d_in[4];
    const float* w2_1 = (const float*)d_in[5];
    const float* w3_1 = (const float*)d_in[6];
    const float* wc1  = (const float*)d_in[7];
    const float* a11  = (const float*)d_in[8];
    const float* a21  = (const float*)d_in[9];
    const float* W2t  = (const float*)d_in[10];
    const float* w2_2 = (const float*)d_in[11];
    const float* w3_2 = (const float*)d_in[12];
    const float* wc2  = (const float*)d_in[13];
    const float* a12  = (const float*)d_in[14];
    const float* a22  = (const float*)d_in[15];
    const float* A1   = (const float*)d_in[16];
    const float* b1   = (const float*)d_in[17];
    const float* ln_g = (const float*)d_in[18];
    const float* ln_b = (const float*)d_in[19];
    const float* A2   = (const float*)d_in[20];
    const float* b2   = (const float*)d_in[21];
    float* outp = (float*)d_out;

    static bool attr_done = false;
    if (!attr_done) {
        cudaFuncSetAttribute((const void*)mma_gemm_k<false, 0>,
                             cudaFuncAttributeMaxDynamicSharedMemorySize, SMEMB);
        cudaFuncSetAttribute((const void*)mma_gemm_k<false, 1>,
                             cudaFuncAttributeMaxDynamicSharedMemorySize, SMEMB);
        cudaFuncSetAttribute((const void*)mma_gemm_k<true, 0>,
                             cudaFuncAttributeMaxDynamicSharedMemorySize, SMEMB);
        attr_done = true;
    }

    float *hidden, *proj, *x4, *s1, *sn, *se, *y, *edge, *e4, *u2, *zpart,
          *invZe, *invZn, *x1, *xW, *sem, *comb, *hpre, *gc, *s1max, *snmax, *semax;
    cudaGetSymbolAddress((void**)&hidden, g_hidden);
    cudaGetSymbolAddress((void**)&proj,   g_proj);
    cudaGetSymbolAddress((void**)&x4,     g_x4);
    cudaGetSymbolAddress((void**)&s1,     g_s1);
    cudaGetSymbolAddress((void**)&sn,     g_sn);
    cudaGetSymbolAddress((void**)&se,     g_se);
    cudaGetSymbolAddress((void**)&y,      g_y);
    cudaGetSymbolAddress((void**)&edge,   g_edge);
    cudaGetSymbolAddress((void**)&e4,     g_e4);
    cudaGetSymbolAddress((void**)&u2,     g_u2);
    cudaGetSymbolAddress((void**)&zpart,  g_zpart);
    cudaGetSymbolAddress((void**)&invZe,  g_invZe);
    cudaGetSymbolAddress((void**)&invZn,  g_invZn);
    cudaGetSymbolAddress((void**)&x1,     g_x1);
    cudaGetSymbolAddress((void**)&xW,     g_xW);
    cudaGetSymbolAddress((void**)&sem,    g_sem);
    cudaGetSymbolAddress((void**)&comb,   g_comb);
    cudaGetSymbolAddress((void**)&hpre,   g_hpre);
    cudaGetSymbolAddress((void**)&gc,     g_c);
    cudaGetSymbolAddress((void**)&s1max,  g_s1max);
    cudaGetSymbolAddress((void**)&snmax,  g_snmax);
    cudaGetSymbolAddress((void**)&semax,  g_semax);

    auto grid = [](int M, int N, int Z) {
        return dim3((N + 63) / 64, (M + 127) / 128, Z);
    };

    dot_scalar_k<<<1, 128>>>(wc1, a11, gc + 0, Ff);
    dot_scalar_k<<<1, 128>>>(wc2, a12, gc + 1, HH);
    gather_k<<<ROWS, 128>>>(inp, emb, hidden);

    // proj = hidden @ Wp^T + bp
    mma_gemm_k<true, 0><<<grid(ROWS, HH, 1), 256, SMEMB>>>(
        hidden, Wp, bp, nullptr, proj, ROWS, HH, Ff, Ff, Ff, HH, 0, 0, 0, 0);

    // ================= layer 1 (alpha 0.1, ELU, no transfer) =================
    mma_gemm_k<false, 0><<<grid(ROWS, Ff, 1), 256, SMEMB>>>(
        hidden, w2_1, nullptr, nullptr, x4, ROWS, Ff, Ff, Ff, Ff, Ff, 0, 0, 0, 0);
    rowdots_k<<<ROWS, 128>>>(x4, a11 + Ff, a21, gc + 0, 0.1f, s1, sn, Ff);
    bmax_k<<<Bb, 256>>>(s1, s1max, Nn);
    bmax_k<<<Bb, 256>>>(sn, snmax, Nn);
    build_y_k<<<ROWS, 128>>>(hidden, s1, s1max, y);
    // edge_un (+Z in col 300) = HT @ y  (batched)
    mma_gemm_k<false, 0><<<grid(Ee, YW, Bb), 256, SMEMB>>>(
        HT, y, nullptr, nullptr, edge, Ee, YW, Nn, Nn, YW, YW,
        (long)Ee * Nn, (long)Nn * YW, (long)Ee * YW, 0);
    invze_k<<<(EROWS + 255) / 256, 256>>>(edge, invZe);
    // e4 = (edge/Z) @ w3_1  via rowscale
    mma_gemm_k<false, 0><<<grid(EROWS, Ff, 1), 256, SMEMB>>>(
        edge, w3_1, nullptr, invZe, e4, EROWS, Ff, Ff, YW, Ff, Ff, 0, 0, 0, 0);
    rowdot_k<<<EROWS, 128>>>(e4, a21 + Ff, se, Ff);
    bmax_k<<<Bb, 256>>>(se, semax, Ee);
    attn_build_k<<<dim3(Nn / 32, Ee / 32, Bb), dim3(32, 8)>>>(
        HT, sn, se, snmax, semax, invZe, u2, zpart, 0.1f);
    zsum_k<<<(ROWS + 255) / 256, 256>>>(zpart, invZn);
    // x1 = elu( (u2 @ edge_un) * invZn )
    mma_gemm_k<false, 1><<<grid(Nn, Ff, Bb), 256, SMEMB>>>(
        u2, edge, nullptr, invZn, x1, Nn, Ff, Ee, Ee, YW, Ff,
        (long)Nn * Ee, (long)Ee * YW, (long)Nn * Ff, Nn);

    // ================= layer 2 (alpha 0.2, no ELU, transfer W2t) =============
    mma_gemm_k<false, 0><<<grid(ROWS, HH, 1), 256, SMEMB>>>(
        x1, w2_2, nullptr, nullptr, x4, ROWS, HH, Ff, Ff, HH, HH, 0, 0, 0, 0);
    mma_gemm_k<false, 0><<<grid(ROWS, HH, 1), 256, SMEMB>>>(
        x1, W2t, nullptr, nullptr, xW, ROWS, HH, Ff, Ff, HH, HH, 0, 0, 0, 0);
    rowdots_k<<<ROWS, 128>>>(x4, a12 + HH, a22, gc + 1, 0.2f, s1, sn, HH);
    bmax_k<<<Bb, 256>>>(s1, s1max, Nn);
    bmax_k<<<Bb, 256>>>(sn, snmax, Nn);
    build_y_k<<<ROWS, 128>>>(xW, s1, s1max, y);
    mma_gemm_k<false, 0><<<grid(Ee, YW, Bb), 256, SMEMB>>>(
        HT, y, nullptr, nullptr, edge, Ee, YW, Nn, Nn, YW, YW,
        (long)Ee * Nn, (long)Nn * YW, (long)Ee * YW, 0);
    invze_k<<<(EROWS + 255) / 256, 256>>>(edge, invZe);
    mma_gemm_k<false, 0><<<grid(EROWS, HH, 1), 256, SMEMB>>>(
        edge, w3_2, nullptr, invZe, e4, EROWS, HH, HH, YW, HH, HH, 0, 0, 0, 0);
    rowdot_k<<<EROWS, 128>>>(e4, a22 + HH, se, HH);
    bmax_k<<<Bb, 256>>>(se, semax, Ee);
    attn_build_k<<<dim3(Nn / 32, Ee / 32, Bb), dim3(32, 8)>>>(
        HT, sn, se, snmax, semax, invZe, u2, zpart, 0.2f);
    zsum_k<<<(ROWS + 255) / 256, 256>>>(zpart, invZn);
    mma_gemm_k<false, 0><<<grid(Nn, HH, Bb), 256, SMEMB>>>(
        u2, edge, nullptr, invZn, sem, Nn, HH, Ee, Ee, YW, HH,
        (long)Nn * Ee, (long)Ee * YW, (long)Nn * HH, Nn);

    // ================= head ==================================================
    concat_k<<<ROWS, 128>>>(proj, sem, comb);
    mma_gemm_k<true, 0><<<grid(ROWS, HH, 1), 256, SMEMB>>>(
        comb, A1, b1, nullptr, hpre, ROWS, HH, 2 * HH, 2 * HH, 2 * HH, HH, 0, 0, 0, 0);
    final_k<<<ROWS, 128>>>(hpre, proj, sem, ln_g, ln_b, A2, b2, outp);
}

// round 6
// speedup vs baseline: 3.7063x; 1.1594x over previous
#include <cuda_runtime.h>
#include <math.h>

#define Bb 32
#define Nn 1024
#define Ee 512
#define Ff 300
#define HH 300
#define Vv 50001

constexpr int ROWS  = Bb * Nn;   // 32768
constexpr int EROWS = Bb * Ee;   // 16384
constexpr int YW    = 304;       // y/edge row width (300 data + w/Z + pad)
constexpr int SSTG  = 128 * 36 + 32 * 72;      // floats per stage (A + B)
constexpr int SMEMB = SSTG * 3 * 4;            // 82944 B, 3 stages

// ---------------- scratch ----------------------------------------------------
__device__ float g_hidden[ROWS * Ff];
__device__ float g_proj  [ROWS * HH];
__device__ float g_x4    [ROWS * Ff];
__device__ float g_s1    [ROWS];
__device__ float g_sn    [ROWS];
__device__ float g_se    [EROWS];
__device__ float g_y     [ROWS * YW];
__device__ float g_edge  [EROWS * YW];
__device__ float g_e4    [EROWS * Ff];
__device__ float g_u2    [Bb * Nn * Ee];
__device__ float g_zpart [ROWS * 16];
__device__ float g_invZe [EROWS];
__device__ float g_invZn [ROWS];
__device__ float g_x1    [ROWS * Ff];
__device__ float g_xW    [ROWS * HH];
__device__ float g_sem   [ROWS * HH];
__device__ float g_comb  [ROWS * 2 * HH];
__device__ float g_hpre  [ROWS * HH];
__device__ float g_c     [2];
__device__ float g_s1max [Bb];
__device__ float g_snmax [Bb];
__device__ float g_semax [Bb];
__device__ float g_wt    [720000];   // tf32-rounded weights

// ---------------- tf32 helpers ----------------------------------------------
__device__ __forceinline__ unsigned to_tf32(float x) {
    unsigned r;
    asm("cvt.rna.tf32.f32 %0, %1;" : "=r"(r) : "f"(x));
    return r;
}
__device__ __forceinline__ float rtf(float x) { return __uint_as_float(to_tf32(x)); }

__device__ __forceinline__ void mma_tf32(float* d, const unsigned* a, const unsigned* b) {
    asm volatile(
        "mma.sync.aligned.m16n8k8.row.col.f32.tf32.tf32.f32 "
        "{%0,%1,%2,%3}, {%4,%5,%6,%7}, {%8,%9}, {%0,%1,%2,%3};"
        : "+f"(d[0]), "+f"(d[1]), "+f"(d[2]), "+f"(d[3])
        : "r"(a[0]), "r"(a[1]), "r"(a[2]), "r"(a[3]), "r"(b[0]), "r"(b[1]));
}

__device__ __forceinline__ void cp16(void* smem_dst, const void* gsrc, bool pred) {
    unsigned d = (unsigned)__cvta_generic_to_shared(smem_dst);
    int sz = pred ? 16 : 0;
    asm volatile("cp.async.ca.shared.global [%0], [%1], 16, %2;" :: "r"(d), "l"(gsrc), "r"(sz));
}

// ---------------- tensor-core GEMM, cp.async 3-stage -------------------------
// Inputs MUST already be tf32-rounded. C = rowscale(A@B) (+bias) (ELU) (tf32 round).
// A:[M,K] lda. B:[K,N] ldb (or [N,K] if TRANSB). Block 128x64, 128 thr,
// warp grid 2x2, warp tile 64x32.
template <bool TRANSB, int ACT, bool ROUND>
__global__ void __launch_bounds__(128)
mma_gemm_k(const float* __restrict__ A, const float* __restrict__ B,
           const float* __restrict__ bias, const float* __restrict__ rowscale,
           float* __restrict__ C,
           int M, int N, int K, int lda, int ldb, int ldc,
           long sA, long sB, long sC, long sScale)
{
    extern __shared__ float sm[];
    constexpr int BOFF = 128 * 36;

    A += (long)blockIdx.z * sA;
    B += (long)blockIdx.z * sB;
    C += (long)blockIdx.z * sC;
    const float* rs = rowscale ? rowscale + (long)blockIdx.z * sScale : nullptr;

    const int tid  = threadIdx.x;
    const int warp = tid >> 5, lane = tid & 31;
    const int g    = lane >> 2, tig = lane & 3;
    const int wm   = warp >> 1, wn = warp & 1;
    const int m0   = blockIdx.y * 128, n0 = blockIdx.x * 64;

    float acc[4][4][4];
#pragma unroll
    for (int i = 0; i < 4; ++i)
#pragma unroll
        for (int j = 0; j < 4; ++j)
#pragma unroll
            for (int l = 0; l < 4; ++l) acc[i][j][l] = 0.f;

    const int kt = (K + 31) / 32;

    auto issue = [&](int t, int st) {
        int k0 = t * 32;
        float* As = sm + st * SSTG;
        float* Bs = As + BOFF;
#pragma unroll
        for (int i = 0; i < 8; ++i) {          // A: 128x32
            int f = tid + i * 128;
            int row = f >> 3, c4 = (f & 7) * 4;
            int gm = m0 + row, gk = k0 + c4;
            bool p = (gm < M) && (gk < K);
            cp16(&As[row * 36 + c4], p ? (A + (long)gm * lda + gk) : A, p);
        }
#pragma unroll
        for (int i = 0; i < 4; ++i) {
            int f = tid + i * 128;
            if (TRANSB) {                       // BsT: [n=64][36]
                int nr = f >> 3, k4 = (f & 7) * 4;
                int gn = n0 + nr, gk = k0 + k4;
                bool p = (gn < N) && (gk < K);
                cp16(&Bs[nr * 36 + k4], p ? (B + (long)gn * ldb + gk) : B, p);
            } else {                            // Bs: [k=32][72]
                int row = f >> 4, c4 = (f & 15) * 4;
                int gk = k0 + row, gn = n0 + c4;
                bool p = (gk < K) && (gn < N);
                cp16(&Bs[row * 72 + c4], p ? (B + (long)gk * ldb + gn) : B, p);
            }
        }
        asm volatile("cp.async.commit_group;");
    };

    issue(0, 0);
    if (kt > 1) issue(1, 1);

    for (int t = 0; t < kt; ++t) {
        asm volatile("cp.async.wait_group 1;");
        __syncthreads();
        if (t + 2 < kt) issue(t + 2, (t + 2) % 3);

        const float* As = sm + (t % 3) * SSTG;
        const float* Bs = As + BOFF;
#pragma unroll
        for (int ks = 0; ks < 4; ++ks) {
            const int kb = ks * 8;
            unsigned af[4][4], bf[4][2];
#pragma unroll
            for (int mi = 0; mi < 4; ++mi) {
                int r = wm * 64 + mi * 16 + g;
                af[mi][0] = __float_as_uint(As[(r    ) * 36 + kb + tig]);
                af[mi][1] = __float_as_uint(As[(r + 8) * 36 + kb + tig]);
                af[mi][2] = __float_as_uint(As[(r    ) * 36 + kb + tig + 4]);
                af[mi][3] = __float_as_uint(As[(r + 8) * 36 + kb + tig + 4]);
            }
#pragma unroll
            for (int ni = 0; ni < 4; ++ni) {
                int c = wn * 32 + ni * 8 + g;
                if (TRANSB) {
                    bf[ni][0] = __float_as_uint(Bs[c * 36 + kb + tig]);
                    bf[ni][1] = __float_as_uint(Bs[c * 36 + kb + tig + 4]);
                } else {
                    bf[ni][0] = __float_as_uint(Bs[(kb + tig    ) * 72 + c]);
                    bf[ni][1] = __float_as_uint(Bs[(kb + tig + 4) * 72 + c]);
                }
            }
#pragma unroll
            for (int mi = 0; mi < 4; ++mi)
#pragma unroll
                for (int ni = 0; ni < 4; ++ni)
                    mma_tf32(acc[mi][ni], af[mi], bf[ni]);
        }
        __syncthreads();
    }

#pragma unroll
    for (int mi = 0; mi < 4; ++mi) {
#pragma unroll
        for (int ni = 0; ni < 4; ++ni) {
            int r = m0 + wm * 64 + mi * 16 + g;
            int c = n0 + wn * 32 + ni * 8 + tig * 2;
            if (c >= N) continue;
            float bx = bias ? bias[c] : 0.f;
            float by = bias ? bias[c + 1] : 0.f;
#pragma unroll
            for (int h = 0; h < 2; ++h) {
                int rr = r + h * 8;
                if (rr >= M) continue;
                float sc = rs ? rs[rr] : 1.f;
                float vx = acc[mi][ni][h * 2 + 0] * sc + bx;
                float vy = acc[mi][ni][h * 2 + 1] * sc + by;
                if (ACT == 1) {
                    vx = (vx > 0.f) ? vx : expm1f(vx);
                    vy = (vy > 0.f) ? vy : expm1f(vy);
                }
                if (ROUND) { vx = rtf(vx); vy = rtf(vy); }
                *(float2*)(C + (long)rr * ldc + c) = make_float2(vx, vy);
            }
        }
    }
}

// ---------------- small kernels ---------------------------------------------
__global__ void cvt_k(const float* __restrict__ src, float* __restrict__ dst, int n4)
{
    int i = blockIdx.x * 256 + threadIdx.x;
    if (i < n4) {
        float4 v = ((const float4*)src)[i];
        v.x = rtf(v.x); v.y = rtf(v.y); v.z = rtf(v.z); v.w = rtf(v.w);
        ((float4*)dst)[i] = v;
    }
}

__global__ void gather_k(const int* __restrict__ idx,
                         const float* __restrict__ emb, float* __restrict__ out)
{
    int row = blockIdx.x;
    int id = idx[row];
    id = max(0, min(id, Vv - 1));
    const float4* src = (const float4*)(emb + (long)id * Ff);
    float4* dst = (float4*)(out + (long)row * Ff);
    int c = threadIdx.x;
    if (c < Ff / 4) {
        float4 v = src[c];
        v.x = rtf(v.x); v.y = rtf(v.y); v.z = rtf(v.z); v.w = rtf(v.w);
        dst[c] = v;
    }
}

__global__ void dot_scalar_k(const float* __restrict__ a, const float* __restrict__ b,
                             float* __restrict__ out, int K)
{
    __shared__ float sh[128];
    float s = 0.f;
    for (int c = threadIdx.x; c < K; c += 128) s += a[c] * b[c];
    sh[threadIdx.x] = s; __syncthreads();
    for (int o = 64; o > 0; o >>= 1) {
        if (threadIdx.x < o) sh[threadIdx.x] += sh[threadIdx.x + o];
        __syncthreads();
    }
    if (threadIdx.x == 0) *out = sh[0];
}

__global__ void rowdots_k(const float* __restrict__ X, const float* __restrict__ v1,
                          const float* __restrict__ v2, const float* __restrict__ cptr,
                          float alpha, float* __restrict__ o1, float* __restrict__ o2, int K)
{
    int row = blockIdx.x;
    const float* x = X + (long)row * K;
    float s1 = 0.f, s2 = 0.f;
    for (int c = threadIdx.x; c < K; c += 128) {
        float xv = x[c];
        s1 += xv * v1[c];
        s2 += xv * v2[c];
    }
    __shared__ float r1[128], r2[128];
    r1[threadIdx.x] = s1; r2[threadIdx.x] = s2; __syncthreads();
    for (int o = 64; o > 0; o >>= 1) {
        if (threadIdx.x < o) { r1[threadIdx.x] += r1[threadIdx.x + o]; r2[threadIdx.x] += r2[threadIdx.x + o]; }
        __syncthreads();
    }
    if (threadIdx.x == 0) {
        float t = *cptr + r1[0];
        o1[row] = (t >= 0.f) ? t : alpha * t;
        o2[row] = r2[0];
    }
}

__global__ void rowdot_k(const float* __restrict__ X, const float* __restrict__ v,
                         float* __restrict__ o, int K)
{
    int row = blockIdx.x;
    const float* x = X + (long)row * K;
    float s = 0.f;
    for (int c = threadIdx.x; c < K; c += 128) s += x[c] * v[c];
    __shared__ float sh[128];
    sh[threadIdx.x] = s; __syncthreads();
    for (int o2 = 64; o2 > 0; o2 >>= 1) {
        if (threadIdx.x < o2) sh[threadIdx.x] += sh[threadIdx.x + o2];
        __syncthreads();
    }
    if (threadIdx.x == 0) o[row] = sh[0];
}

__global__ void bmax_k(const float* __restrict__ X, float* __restrict__ out, int len)
{
    __shared__ float sh[256];
    int b = blockIdx.x;
    const float* x = X + (long)b * len;
    float m = -3.0e38f;
    for (int i = threadIdx.x; i < len; i += 256) m = fmaxf(m, x[i]);
    sh[threadIdx.x] = m; __syncthreads();
    for (int o = 128; o > 0; o >>= 1) {
        if (threadIdx.x < o) sh[threadIdx.x] = fmaxf(sh[threadIdx.x], sh[threadIdx.x + o]);
        __syncthreads();
    }
    if (threadIdx.x == 0) out[b] = sh[0];
}

// y[row][0:300] = tf32(w*x), y[row][300] = tf32(w), rest 0; w = exp(s1-max_b)
__global__ void build_y_k(const float* __restrict__ X, const float* __restrict__ s1,
                          const float* __restrict__ s1max, float* __restrict__ y)
{
    int row = blockIdx.x;
    int b = row >> 10;
    float w = expf(s1[row] - s1max[b]);
    const float* x = X + (long)row * Ff;
    float* yy = y + (long)row * YW;
    for (int c = threadIdx.x; c < YW; c += 128)
        yy[c] = (c < Ff) ? rtf(w * x[c]) : ((c == Ff) ? rtf(w) : 0.f);
}

__global__ void invze_k(const float* __restrict__ edge, float* __restrict__ invZe)
{
    int i = blockIdx.x * 256 + threadIdx.x;
    if (i < EROWS) {
        float z = edge[(long)i * YW + Ff];
        invZe[i] = (z > 0.f) ? 1.f / z : 0.f;
    }
}

// u2[b,n,e] = tf32(mask * exp(leaky(sn+se)-shift) * invZe[b,e]); zpart = tile row sums
__global__ void attn_build_k(const float* __restrict__ HT, const float* __restrict__ sn,
                             const float* __restrict__ se, const float* __restrict__ snmax,
                             const float* __restrict__ semax, const float* __restrict__ invZe,
                             float* __restrict__ u2, float* __restrict__ zpart, float alpha)
{
    __shared__ float t[32][33];
    int b  = blockIdx.z;
    int n0 = blockIdx.x * 32, e0 = blockIdx.y * 32;
    int tx = threadIdx.x, ty = threadIdx.y;   // (32,8)

    float sh = snmax[b] + semax[b];
    sh = (sh >= 0.f) ? sh : alpha * sh;

    const float* src = HT + (long)b * Ee * Nn;
    float snv = sn[(long)b * Nn + n0 + tx];
#pragma unroll
    for (int i = 0; i < 32; i += 8) {
        int e = e0 + ty + i;
        float sev = se[(long)b * Ee + e];
        float ht  = src[(long)e * Nn + n0 + tx];
        float v = snv + sev;
        v = (v >= 0.f) ? v : alpha * v;
        t[ty + i][tx] = (ht > 0.f) ? expf(v - sh) : 0.f;
    }
    __syncthreads();

    float iz = invZe[(long)b * Ee + e0 + tx];
    float* dst = u2 + (long)b * Nn * Ee;
#pragma unroll
    for (int i = 0; i < 32; i += 8) {
        int n = n0 + ty + i;
        dst[(long)n * Ee + e0 + tx] = rtf(t[tx][ty + i] * iz);
    }

    if (ty == 0) {
        float s = 0.f;
#pragma unroll
        for (int e = 0; e < 32; ++e) s += t[e][tx];
        zpart[((long)b * Nn + n0 + tx) * 16 + blockIdx.y] = s;
    }
}

__global__ void zsum_k(const float* __restrict__ zpart, float* __restrict__ invZn)
{
    int i = blockIdx.x * 256 + threadIdx.x;
    if (i < ROWS) {
        float s = 0.f;
#pragma unroll
        for (int j = 0; j < 16; ++j) s += zpart[(long)i * 16 + j];
        invZn[i] = (s > 0.f) ? 1.f / s : 0.f;
    }
}

__global__ void concat_k(const float* __restrict__ proj, const float* __restrict__ sem,
                         float* __restrict__ comb)
{
    int row = blockIdx.x;
    float* dst = comb + (long)row * (2 * HH);
    const float* p = proj + (long)row * HH;
    const float* s = sem + (long)row * HH;
    for (int c = threadIdx.x; c < HH; c += 128) {
        dst[c]      = rtf(p[c]);
        dst[HH + c] = rtf(s[c]);
    }
}

__global__ void final_k(const float* __restrict__ hpre, const float* __restrict__ proj,
                        const float* __restrict__ sem, const float* __restrict__ ln_g,
                        const float* __restrict__ ln_b, const float* __restrict__ A2,
                        const float* __restrict__ b2, float* __restrict__ out)
{
    int row = blockIdx.x;
    int tid = threadIdx.x;
    __shared__ float hs[HH];
    __shared__ float red[128];
    const float* hp = hpre + (long)row * HH;

    float s = 0.f;
    for (int c = tid; c < HH; c += 128) {
        float t = tanhf(hp[c]);
        hs[c] = t;
        s += t;
    }
    red[tid] = s; __syncthreads();
    for (int o = 64; o > 0; o >>= 1) {
        if (tid < o) red[tid] += red[tid + o];
        __syncthreads();
    }
    float mean = red[0] / (float)HH;
    __syncthreads();

    float vs = 0.f;
    for (int c = tid; c < HH; c += 128) { float d = hs[c] - mean; vs += d * d; }
    red[tid] = vs; __syncthreads();
    for (int o = 64; o > 0; o >>= 1) {
        if (tid < o) red[tid] += red[tid + o];
        __syncthreads();
    }
    float rstd = rsqrtf(red[0] / (float)HH + 1e-5f);
    __syncthreads();

    float gdot = 0.f;
    for (int c = tid; c < HH; c += 128) {
        float hn = (hs[c] - mean) * rstd * ln_g[c] + ln_b[c];
        gdot += hn * A2[c];
    }
    red[tid] = gdot; __syncthreads();
    for (int o = 64; o > 0; o >>= 1) {
        if (tid < o) red[tid] += red[tid + o];
        __syncthreads();
    }
    float gate = 1.f / (1.f + expf(-(red[0] + b2[0])));
    __syncthreads();

    const float* p = proj + (long)row * HH;
    const float* se = sem + (long)row * HH;
    float* o = out + (long)row * HH;
    for (int c = tid; c < HH; c += 128)
        o[c] = gate * se[c] + (1.f - gate) * p[c];
}

// ---------------- launcher ---------------------------------------------------
extern "C" void kernel_launch(void* const* d_in, const int* in_sizes, int n_in,
                              void* d_out, int out_size)
{
    const int*   inp  = (const int*)d_in[0];
    const float* HT   = (const float*)d_in[1];
    const float* emb  = (const float*)d_in[2];
    const float* Wp   = (const float*)d_in[3];
    const float* bp   = (const float*)d_in[4];
    const float* w2_1 = (const float*)d_in[5];
    const float* w3_1 = (const float*)d_in[6];
    const float* wc1  = (const float*)d_in[7];
    const float* a11  = (const float*)d_in[8];
    const float* a21  = (const float*)d_in[9];
    const float* W2t  = (const float*)d_in[10];
    const float* w2_2 = (const float*)d_in[11];
    const float* w3_2 = (const float*)d_in[12];
    const float* wc2  = (const float*)d_in[13];
    const float* a12  = (const float*)d_in[14];
    const float* a22  = (const float*)d_in[15];
    const float* A1   = (const float*)d_in[16];
    const float* b1   = (const float*)d_in[17];
    const float* ln_g = (const float*)d_in[18];
    const float* ln_b = (const float*)d_in[19];
    const float* A2   = (const float*)d_in[20];
    const float* b2   = (const float*)d_in[21];
    float* outp = (float*)d_out;

    static bool attr_done = false;
    if (!attr_done) {
        cudaFuncSetAttribute((const void*)mma_gemm_k<false, 0, false>,
                             cudaFuncAttributeMaxDynamicSharedMemorySize, SMEMB);
        cudaFuncSetAttribute((const void*)mma_gemm_k<false, 0, true>,
                             cudaFuncAttributeMaxDynamicSharedMemorySize, SMEMB);
        cudaFuncSetAttribute((const void*)mma_gemm_k<false, 1, true>,
                             cudaFuncAttributeMaxDynamicSharedMemorySize, SMEMB);
        cudaFuncSetAttribute((const void*)mma_gemm_k<true, 0, false>,
                             cudaFuncAttributeMaxDynamicSharedMemorySize, SMEMB);
        attr_done = true;
    }

    float *hidden, *proj, *x4, *s1, *sn, *se, *y, *edge, *e4, *u2, *zpart,
          *invZe, *invZn, *x1, *xW, *sem, *comb, *hpre, *gc, *s1max, *snmax, *semax, *wt;
    cudaGetSymbolAddress((void**)&hidden, g_hidden);
    cudaGetSymbolAddress((void**)&proj,   g_proj);
    cudaGetSymbolAddress((void**)&x4,     g_x4);
    cudaGetSymbolAddress((void**)&s1,     g_s1);
    cudaGetSymbolAddress((void**)&sn,     g_sn);
    cudaGetSymbolAddress((void**)&se,     g_se);
    cudaGetSymbolAddress((void**)&y,      g_y);
    cudaGetSymbolAddress((void**)&edge,   g_edge);
    cudaGetSymbolAddress((void**)&e4,     g_e4);
    cudaGetSymbolAddress((void**)&u2,     g_u2);
    cudaGetSymbolAddress((void**)&zpart,  g_zpart);
    cudaGetSymbolAddress((void**)&invZe,  g_invZe);
    cudaGetSymbolAddress((void**)&invZn,  g_invZn);
    cudaGetSymbolAddress((void**)&x1,     g_x1);
    cudaGetSymbolAddress((void**)&xW,     g_xW);
    cudaGetSymbolAddress((void**)&sem,    g_sem);
    cudaGetSymbolAddress((void**)&comb,   g_comb);
    cudaGetSymbolAddress((void**)&hpre,   g_hpre);
    cudaGetSymbolAddress((void**)&gc,     g_c);
    cudaGetSymbolAddress((void**)&s1max,  g_s1max);
    cudaGetSymbolAddress((void**)&snmax,  g_snmax);
    cudaGetSymbolAddress((void**)&semax,  g_semax);
    cudaGetSymbolAddress((void**)&wt,     g_wt);

    float* Wpc  = wt;
    float* w21c = wt + 90000;
    float* w31c = wt + 180000;
    float* W2tc = wt + 270000;
    float* w22c = wt + 360000;
    float* w32c = wt + 450000;
    float* A1c  = wt + 540000;

    auto grid = [](int M, int N, int Z) {
        return dim3((N + 63) / 64, (M + 127) / 128, Z);
    };

    // tf32-round weights into scratch (idempotent, graph-capturable)
    cvt_k<<<(22500 + 255) / 256, 256>>>(Wp,   Wpc,  22500);
    cvt_k<<<(22500 + 255) / 256, 256>>>(w2_1, w21c, 22500);
    cvt_k<<<(22500 + 255) / 256, 256>>>(w3_1, w31c, 22500);
    cvt_k<<<(22500 + 255) / 256, 256>>>(W2t,  W2tc, 22500);
    cvt_k<<<(22500 + 255) / 256, 256>>>(w2_2, w22c, 22500);
    cvt_k<<<(22500 + 255) / 256, 256>>>(w3_2, w32c, 22500);
    cvt_k<<<(45000 + 255) / 256, 256>>>(A1,   A1c,  45000);

    dot_scalar_k<<<1, 128>>>(wc1, a11, gc + 0, Ff);
    dot_scalar_k<<<1, 128>>>(wc2, a12, gc + 1, HH);
    gather_k<<<ROWS, 128>>>(inp, emb, hidden);

    // proj = hidden @ Wp^T + bp
    mma_gemm_k<true, 0, false><<<grid(ROWS, HH, 1), 128, SMEMB>>>(
        hidden, Wpc, bp, nullptr, proj, ROWS, HH, Ff, Ff, Ff, HH, 0, 0, 0, 0);

    // ================= layer 1 (alpha 0.1, ELU, no transfer) =================
    mma_gemm_k<false, 0, false><<<grid(ROWS, Ff, 1), 128, SMEMB>>>(
        hidden, w21c, nullptr, nullptr, x4, ROWS, Ff, Ff, Ff, Ff, Ff, 0, 0, 0, 0);
    rowdots_k<<<ROWS, 128>>>(x4, a11 + Ff, a21, gc + 0, 0.1f, s1, sn, Ff);
    bmax_k<<<Bb, 256>>>(s1, s1max, Nn);
    bmax_k<<<Bb, 256>>>(sn, snmax, Nn);
    build_y_k<<<ROWS, 128>>>(hidden, s1, s1max, y);
    mma_gemm_k<false, 0, true><<<grid(Ee, YW, Bb), 128, SMEMB>>>(
        HT, y, nullptr, nullptr, edge, Ee, YW, Nn, Nn, YW, YW,
        (long)Ee * Nn, (long)Nn * YW, (long)Ee * YW, 0);
    invze_k<<<(EROWS + 255) / 256, 256>>>(edge, invZe);
    mma_gemm_k<false, 0, false><<<grid(EROWS, Ff, 1), 128, SMEMB>>>(
        edge, w31c, nullptr, invZe, e4, EROWS, Ff, Ff, YW, Ff, Ff, 0, 0, 0, 0);
    rowdot_k<<<EROWS, 128>>>(e4, a21 + Ff, se, Ff);
    bmax_k<<<Bb, 256>>>(se, semax, Ee);
    attn_build_k<<<dim3(Nn / 32, Ee / 32, Bb), dim3(32, 8)>>>(
        HT, sn, se, snmax, semax, invZe, u2, zpart, 0.1f);
    zsum_k<<<(ROWS + 255) / 256, 256>>>(zpart, invZn);
    mma_gemm_k<false, 1, true><<<grid(Nn, Ff, Bb), 128, SMEMB>>>(
        u2, edge, nullptr, invZn, x1, Nn, Ff, Ee, Ee, YW, Ff,
        (long)Nn * Ee, (long)Ee * YW, (long)Nn * Ff, Nn);

    // ================= layer 2 (alpha 0.2, no ELU, transfer W2t) =============
    mma_gemm_k<false, 0, false><<<grid(ROWS, HH, 1), 128, SMEMB>>>(
        x1, w22c, nullptr, nullptr, x4, ROWS, HH, Ff, Ff, HH, HH, 0, 0, 0, 0);
    mma_gemm_k<false, 0, false><<<grid(ROWS, HH, 1), 128, SMEMB>>>(
        x1, W2tc, nullptr, nullptr, xW, ROWS, HH, Ff, Ff, HH, HH, 0, 0, 0, 0);
    rowdots_k<<<ROWS, 128>>>(x4, a12 + HH, a22, gc + 1, 0.2f, s1, sn, HH);
    bmax_k<<<Bb, 256>>>(s1, s1max, Nn);
    bmax_k<<<Bb, 256>>>(sn, snmax, Nn);
    build_y_k<<<ROWS, 128>>>(xW, s1, s1max, y);
    mma_gemm_k<false, 0, true><<<grid(Ee, YW, Bb), 128, SMEMB>>>(
        HT, y, nullptr, nullptr, edge, Ee, YW, Nn, Nn, YW, YW,
        (long)Ee * Nn, (long)Nn * YW, (long)Ee * YW, 0);
    invze_k<<<(EROWS + 255) / 256, 256>>>(edge, invZe);
    mma_gemm_k<false, 0, false><<<grid(EROWS, HH, 1), 128, SMEMB>>>(
        edge, w32c, nullptr, invZe, e4, EROWS, HH, HH, YW, HH, HH, 0, 0, 0, 0);
    rowdot_k<<<EROWS, 128>>>(e4, a22 + HH, se, HH);
    bmax_k<<<Bb, 256>>>(se, semax, Ee);
    attn_build_k<<<dim3(Nn / 32, Ee / 32, Bb), dim3(32, 8)>>>(
        HT, sn, se, snmax, semax, invZe, u2, zpart, 0.2f);
    zsum_k<<<(ROWS + 255) / 256, 256>>>(zpart, invZn);
    mma_gemm_k<false, 0, false><<<grid(Nn, HH, Bb), 128, SMEMB>>>(
        u2, edge, nullptr, invZn, sem, Nn, HH, Ee, Ee, YW, HH,
        (long)Nn * Ee, (long)Ee * YW, (long)Nn * HH, Nn);

    // ================= head ==================================================
    concat_k<<<ROWS, 128>>>(proj, sem, comb);
    mma_gemm_k<true, 0, false><<<grid(ROWS, HH, 1), 128, SMEMB>>>(
        comb, A1c, b1, nullptr, hpre, ROWS, HH, 2 * HH, 2 * HH, 2 * HH, HH, 0, 0, 0, 0);
    final_k<<<ROWS, 128>>>(hpre, proj, sem, ln_g, ln_b, A2, b2, outp);
}

// round 7
// speedup vs baseline: 3.7153x; 1.0024x over previous
#include <cuda_runtime.h>
#include <math.h>

#define Bb 32
#define Nn 1024
#define Ee 512
#define Ff 300
#define HH 300
#define Vv 50001

constexpr int ROWS  = Bb * Nn;   // 32768
constexpr int EROWS = Bb * Ee;   // 16384
constexpr int YW    = 304;       // y/edge row width (300 data + w/Z + pad)
constexpr int SSTG  = 128 * 36 + 32 * 72;      // floats per stage (A + B)
constexpr int SMEMB = SSTG * 3 * 4;            // 82944 B, 3 stages

// ---------------- scratch ----------------------------------------------------
__device__ float g_hidden[ROWS * Ff];
__device__ float g_proj  [ROWS * HH];
__device__ float g_x4    [ROWS * Ff];
__device__ float g_s1    [ROWS];
__device__ float g_sn    [ROWS];
__device__ float g_se    [EROWS];
__device__ float g_y     [ROWS * YW];
__device__ float g_edge  [EROWS * YW];
__device__ float g_e4    [EROWS * Ff];
__device__ float g_u2    [Bb * Nn * Ee];
__device__ float g_zpart [ROWS * 16];
__device__ float g_invZe [EROWS];
__device__ float g_invZn [ROWS];
__device__ float g_x1    [ROWS * Ff];
__device__ float g_xW    [ROWS * HH];
__device__ float g_sem   [ROWS * HH];
__device__ float g_comb  [ROWS * 2 * HH];
__device__ float g_hpre  [ROWS * HH];
__device__ float g_c     [2];
__device__ float g_s1max [Bb];
__device__ float g_snmax [Bb];
__device__ float g_semax [Bb];
__device__ float g_wt    [720000];   // tf32-rounded weights

// ---------------- tf32 helpers ----------------------------------------------
__device__ __forceinline__ unsigned to_tf32(float x) {
    unsigned r;
    asm("cvt.rna.tf32.f32 %0, %1;" : "=r"(r) : "f"(x));
    return r;
}
__device__ __forceinline__ float rtf(float x) { return __uint_as_float(to_tf32(x)); }

__device__ __forceinline__ void mma_tf32(float* d, const unsigned* a, const unsigned* b) {
    asm volatile(
        "mma.sync.aligned.m16n8k8.row.col.f32.tf32.tf32.f32 "
        "{%0,%1,%2,%3}, {%4,%5,%6,%7}, {%8,%9}, {%0,%1,%2,%3};"
        : "+f"(d[0]), "+f"(d[1]), "+f"(d[2]), "+f"(d[3])
        : "r"(a[0]), "r"(a[1]), "r"(a[2]), "r"(a[3]), "r"(b[0]), "r"(b[1]));
}

__device__ __forceinline__ void cp16(void* smem_dst, const void* gsrc, bool pred) {
    unsigned d = (unsigned)__cvta_generic_to_shared(smem_dst);
    int sz = pred ? 16 : 0;
    asm volatile("cp.async.ca.shared.global [%0], [%1], 16, %2;" :: "r"(d), "l"(gsrc), "r"(sz));
}

// ---------------- tensor-core GEMM, cp.async 3-stage -------------------------
// Inputs MUST already be tf32-rounded. C = rowscale(A@B) (+bias) (ELU) (tf32 round).
// A:[M,K] lda. B:[K,N] ldb (or [N,K] if TRANSB). Block 128x64, 128 thr,
// warp grid 2x2, warp tile 64x32.
template <bool TRANSB, int ACT, bool ROUND>
__global__ void __launch_bounds__(128)
mma_gemm_k(const float* __restrict__ A, const float* __restrict__ B,
           const float* __restrict__ bias, const float* __restrict__ rowscale,
           float* __restrict__ C,
           int M, int N, int K, int lda, int ldb, int ldc,
           long sA, long sB, long sC, long sScale)
{
    extern __shared__ float sm[];
    constexpr int BOFF = 128 * 36;

    A += (long)blockIdx.z * sA;
    B += (long)blockIdx.z * sB;
    C += (long)blockIdx.z * sC;
    const float* rs = rowscale ? rowscale + (long)blockIdx.z * sScale : nullptr;

    const int tid  = threadIdx.x;
    const int warp = tid >> 5, lane = tid & 31;
    const int g    = lane >> 2, tig = lane & 3;
    const int wm   = warp >> 1, wn = warp & 1;
    const int m0   = blockIdx.y * 128, n0 = blockIdx.x * 64;

    float acc[4][4][4];
#pragma unroll
    for (int i = 0; i < 4; ++i)
#pragma unroll
        for (int j = 0; j < 4; ++j)
#pragma unroll
            for (int l = 0; l < 4; ++l) acc[i][j][l] = 0.f;

    const int kt = (K + 31) / 32;

    auto issue = [&](int t, int st) {
        int k0 = t * 32;
        float* As = sm + st * SSTG;
        float* Bs = As + BOFF;
#pragma unroll
        for (int i = 0; i < 8; ++i) {          // A: 128x32
            int f = tid + i * 128;
            int row = f >> 3, c4 = (f & 7) * 4;
            int gm = m0 + row, gk = k0 + c4;
            bool p = (gm < M) && (gk < K);
            cp16(&As[row * 36 + c4], p ? (A + (long)gm * lda + gk) : A, p);
        }
#pragma unroll
        for (int i = 0; i < 4; ++i) {
            int f = tid + i * 128;
            if (TRANSB) {                       // BsT: [n=64][36]
                int nr = f >> 3, k4 = (f & 7) * 4;
                int gn = n0 + nr, gk = k0 + k4;
                bool p = (gn < N) && (gk < K);
                cp16(&Bs[nr * 36 + k4], p ? (B + (long)gn * ldb + gk) : B, p);
            } else {                            // Bs: [k=32][72]
                int row = f >> 4, c4 = (f & 15) * 4;
                int gk = k0 + row, gn = n0 + c4;
                bool p = (gk < K) && (gn < N);
                cp16(&Bs[row * 72 + c4], p ? (B + (long)gk * ldb + gn) : B, p);
            }
        }
        asm volatile("cp.async.commit_group;");
    };

    issue(0, 0);
    if (kt > 1) issue(1, 1);

    for (int t = 0; t < kt; ++t) {
        asm volatile("cp.async.wait_group 1;");
        __syncthreads();
        if (t + 2 < kt) issue(t + 2, (t + 2) % 3);

        const float* As = sm + (t % 3) * SSTG;
        const float* Bs = As + BOFF;
#pragma unroll
        for (int ks = 0; ks < 4; ++ks) {
            const int kb = ks * 8;
            unsigned af[4][4], bf[4][2];
#pragma unroll
            for (int mi = 0; mi < 4; ++mi) {
                int r = wm * 64 + mi * 16 + g;
                af[mi][0] = __float_as_uint(As[(r    ) * 36 + kb + tig]);
                af[mi][1] = __float_as_uint(As[(r + 8) * 36 + kb + tig]);
                af[mi][2] = __float_as_uint(As[(r    ) * 36 + kb + tig + 4]);
                af[mi][3] = __float_as_uint(As[(r + 8) * 36 + kb + tig + 4]);
            }
#pragma unroll
            for (int ni = 0; ni < 4; ++ni) {
                int c = wn * 32 + ni * 8 + g;
                if (TRANSB) {
                    bf[ni][0] = __float_as_uint(Bs[c * 36 + kb + tig]);
                    bf[ni][1] = __float_as_uint(Bs[c * 36 + kb + tig + 4]);
                } else {
                    bf[ni][0] = __float_as_uint(Bs[(kb + tig    ) * 72 + c]);
                    bf[ni][1] = __float_as_uint(Bs[(kb + tig + 4) * 72 + c]);
                }
            }
#pragma unroll
            for (int mi = 0; mi < 4; ++mi)
#pragma unroll
                for (int ni = 0; ni < 4; ++ni)
                    mma_tf32(acc[mi][ni], af[mi], bf[ni]);
        }
        __syncthreads();
    }

#pragma unroll
    for (int mi = 0; mi < 4; ++mi) {
#pragma unroll
        for (int ni = 0; ni < 4; ++ni) {
            int r = m0 + wm * 64 + mi * 16 + g;
            int c = n0 + wn * 32 + ni * 8 + tig * 2;
            if (c >= N) continue;
            float bx = bias ? bias[c] : 0.f;
            float by = bias ? bias[c + 1] : 0.f;
#pragma unroll
            for (int h = 0; h < 2; ++h) {
                int rr = r + h * 8;
                if (rr >= M) continue;
                float sc = rs ? rs[rr] : 1.f;
                float vx = acc[mi][ni][h * 2 + 0] * sc + bx;
                float vy = acc[mi][ni][h * 2 + 1] * sc + by;
                if (ACT == 1) {
                    vx = (vx > 0.f) ? vx : expm1f(vx);
                    vy = (vy > 0.f) ? vy : expm1f(vy);
                }
                if (ROUND) { vx = rtf(vx); vy = rtf(vy); }
                *(float2*)(C + (long)rr * ldc + c) = make_float2(vx, vy);
            }
        }
    }
}

// ---------------- small kernels ---------------------------------------------
__global__ void cvt_k(const float* __restrict__ src, float* __restrict__ dst, int n4)
{
    int i = blockIdx.x * 256 + threadIdx.x;
    if (i < n4) {
        float4 v = ((const float4*)src)[i];
        v.x = rtf(v.x); v.y = rtf(v.y); v.z = rtf(v.z); v.w = rtf(v.w);
        ((float4*)dst)[i] = v;
    }
}

__global__ void gather_k(const int* __restrict__ idx,
                         const float* __restrict__ emb, float* __restrict__ out)
{
    int row = blockIdx.x;
    int id = idx[row];
    id = max(0, min(id, Vv - 1));
    const float4* src = (const float4*)(emb + (long)id * Ff);
    float4* dst = (float4*)(out + (long)row * Ff);
    int c = threadIdx.x;
    if (c < Ff / 4) {
        float4 v = src[c];
        v.x = rtf(v.x); v.y = rtf(v.y); v.z = rtf(v.z); v.w = rtf(v.w);
        dst[c] = v;
    }
}

__global__ void dot_scalar_k(const float* __restrict__ a, const float* __restrict__ b,
                             float* __restrict__ out, int K)
{
    __shared__ float sh[128];
    float s = 0.f;
    for (int c = threadIdx.x; c < K; c += 128) s += a[c] * b[c];
    sh[threadIdx.x] = s; __syncthreads();
    for (int o = 64; o > 0; o >>= 1) {
        if (threadIdx.x < o) sh[threadIdx.x] += sh[threadIdx.x + o];
        __syncthreads();
    }
    if (threadIdx.x == 0) *out = sh[0];
}

__global__ void rowdots_k(const float* __restrict__ X, const float* __restrict__ v1,
                          const float* __restrict__ v2, const float* __restrict__ cptr,
                          float alpha, float* __restrict__ o1, float* __restrict__ o2, int K)
{
    int row = blockIdx.x;
    const float* x = X + (long)row * K;
    float s1 = 0.f, s2 = 0.f;
    for (int c = threadIdx.x; c < K; c += 128) {
        float xv = x[c];
        s1 += xv * v1[c];
        s2 += xv * v2[c];
    }
    __shared__ float r1[128], r2[128];
    r1[threadIdx.x] = s1; r2[threadIdx.x] = s2; __syncthreads();
    for (int o = 64; o > 0; o >>= 1) {
        if (threadIdx.x < o) { r1[threadIdx.x] += r1[threadIdx.x + o]; r2[threadIdx.x] += r2[threadIdx.x + o]; }
        __syncthreads();
    }
    if (threadIdx.x == 0) {
        float t = *cptr + r1[0];
        o1[row] = (t >= 0.f) ? t : alpha * t;
        o2[row] = r2[0];
    }
}

__global__ void rowdot_k(const float* __restrict__ X, const float* __restrict__ v,
                         float* __restrict__ o, int K)
{
    int row = blockIdx.x;
    const float* x = X + (long)row * K;
    float s = 0.f;
    for (int c = threadIdx.x; c < K; c += 128) s += x[c] * v[c];
    __shared__ float sh[128];
    sh[threadIdx.x] = s; __syncthreads();
    for (int o2 = 64; o2 > 0; o2 >>= 1) {
        if (threadIdx.x < o2) sh[threadIdx.x] += sh[threadIdx.x + o2];
        __syncthreads();
    }
    if (threadIdx.x == 0) o[row] = sh[0];
}

__global__ void bmax_k(const float* __restrict__ X, float* __restrict__ out, int len)
{
    __shared__ float sh[256];
    int b = blockIdx.x;
    const float* x = X + (long)b * len;
    float m = -3.0e38f;
    for (int i = threadIdx.x; i < len; i += 256) m = fmaxf(m, x[i]);
    sh[threadIdx.x] = m; __syncthreads();
    for (int o = 128; o > 0; o >>= 1) {
        if (threadIdx.x < o) sh[threadIdx.x] = fmaxf(sh[threadIdx.x], sh[threadIdx.x + o]);
        __syncthreads();
    }
    if (threadIdx.x == 0) out[b] = sh[0];
}

// y[row][0:300] = tf32(w*x), y[row][300] = tf32(w), rest 0; w = exp(s1-max_b)
__global__ void build_y_k(const float* __restrict__ X, const float* __restrict__ s1,
                          const float* __restrict__ s1max, float* __restrict__ y)
{
    int row = blockIdx.x;
    int b = row >> 10;
    float w = expf(s1[row] - s1max[b]);
    const float* x = X + (long)row * Ff;
    float* yy = y + (long)row * YW;
    for (int c = threadIdx.x; c < YW; c += 128)
        yy[c] = (c < Ff) ? rtf(w * x[c]) : ((c == Ff) ? rtf(w) : 0.f);
}

__global__ void invze_k(const float* __restrict__ edge, float* __restrict__ invZe)
{
    int i = blockIdx.x * 256 + threadIdx.x;
    if (i < EROWS) {
        float z = edge[(long)i * YW + Ff];
        invZe[i] = (z > 0.f) ? 1.f / z : 0.f;
    }
}

// u2[b,n,e] = tf32(mask * exp(leaky(sn+se)-shift) * invZe[b,e]); zpart = tile row sums
__global__ void attn_build_k(const float* __restrict__ HT, const float* __restrict__ sn,
                             const float* __restrict__ se, const float* __restrict__ snmax,
                             const float* __restrict__ semax, const float* __restrict__ invZe,
                             float* __restrict__ u2, float* __restrict__ zpart, float alpha)
{
    __shared__ float t[32][33];
    int b  = blockIdx.z;
    int n0 = blockIdx.x * 32, e0 = blockIdx.y * 32;
    int tx = threadIdx.x, ty = threadIdx.y;   // (32,8)

    float sh = snmax[b] + semax[b];
    sh = (sh >= 0.f) ? sh : alpha * sh;

    const float* src = HT + (long)b * Ee * Nn;
    float snv = sn[(long)b * Nn + n0 + tx];
#pragma unroll
    for (int i = 0; i < 32; i += 8) {
        int e = e0 + ty + i;
        float sev = se[(long)b * Ee + e];
        float ht  = src[(long)e * Nn + n0 + tx];
        float v = snv + sev;
        v = (v >= 0.f) ? v : alpha * v;
        t[ty + i][tx] = (ht > 0.f) ? expf(v - sh) : 0.f;
    }
    __syncthreads();

    float iz = invZe[(long)b * Ee + e0 + tx];
    float* dst = u2 + (long)b * Nn * Ee;
#pragma unroll
    for (int i = 0; i < 32; i += 8) {
        int n = n0 + ty + i;
        dst[(long)n * Ee + e0 + tx] = rtf(t[tx][ty + i] * iz);
    }

    if (ty == 0) {
        float s = 0.f;
#pragma unroll
        for (int e = 0; e < 32; ++e) s += t[e][tx];
        zpart[((long)b * Nn + n0 + tx) * 16 + blockIdx.y] = s;
    }
}

__global__ void zsum_k(const float* __restrict__ zpart, float* __restrict__ invZn)
{
    int i = blockIdx.x * 256 + threadIdx.x;
    if (i < ROWS) {
        float s = 0.f;
#pragma unroll
        for (int j = 0; j < 16; ++j) s += zpart[(long)i * 16 + j];
        invZn[i] = (s > 0.f) ? 1.f / s : 0.f;
    }
}

__global__ void concat_k(const float* __restrict__ proj, const float* __restrict__ sem,
                         float* __restrict__ comb)
{
    int row = blockIdx.x;
    float* dst = comb + (long)row * (2 * HH);
    const float* p = proj + (long)row * HH;
    const float* s = sem + (long)row * HH;
    for (int c = threadIdx.x; c < HH; c += 128) {
        dst[c]      = rtf(p[c]);
        dst[HH + c] = rtf(s[c]);
    }
}

__global__ void final_k(const float* __restrict__ hpre, const float* __restrict__ proj,
                        const float* __restrict__ sem, const float* __restrict__ ln_g,
                        const float* __restrict__ ln_b, const float* __restrict__ A2,
                        const float* __restrict__ b2, float* __restrict__ out)
{
    int row = blockIdx.x;
    int tid = threadIdx.x;
    __shared__ float hs[HH];
    __shared__ float red[128];
    const float* hp = hpre + (long)row * HH;

    float s = 0.f;
    for (int c = tid; c < HH; c += 128) {
        float t = tanhf(hp[c]);
        hs[c] = t;
        s += t;
    }
    red[tid] = s; __syncthreads();
    for (int o = 64; o > 0; o >>= 1) {
        if (tid < o) red[tid] += red[tid + o];
        __syncthreads();
    }
    float mean = red[0] / (float)HH;
    __syncthreads();

    float vs = 0.f;
    for (int c = tid; c < HH; c += 128) { float d = hs[c] - mean; vs += d * d; }
    red[tid] = vs; __syncthreads();
    for (int o = 64; o > 0; o >>= 1) {
        if (tid < o) red[tid] += red[tid + o];
        __syncthreads();
    }
    float rstd = rsqrtf(red[0] / (float)HH + 1e-5f);
    __syncthreads();

    float gdot = 0.f;
    for (int c = tid; c < HH; c += 128) {
        float hn = (hs[c] - mean) * rstd * ln_g[c] + ln_b[c];
        gdot += hn * A2[c];
    }
    red[tid] = gdot; __syncthreads();
    for (int o = 64; o > 0; o >>= 1) {
        if (tid < o) red[tid] += red[tid + o];
        __syncthreads();
    }
    float gate = 1.f / (1.f + expf(-(red[0] + b2[0])));
    __syncthreads();

    const float* p = proj + (long)row * HH;
    const float* se = sem + (long)row * HH;
    float* o = out + (long)row * HH;
    for (int c = tid; c < HH; c += 128)
        o[c] = gate * se[c] + (1.f - gate) * p[c];
}

// ---------------- launcher ---------------------------------------------------
extern "C" void kernel_launch(void* const* d_in, const int* in_sizes, int n_in,
                              void* d_out, int out_size)
{
    const int*   inp  = (const int*)d_in[0];
    const float* HT   = (const float*)d_in[1];
    const float* emb  = (const float*)d_in[2];
    const float* Wp   = (const float*)d_in[3];
    const float* bp   = (const float*)d_in[4];
    const float* w2_1 = (const float*)d_in[5];
    const float* w3_1 = (const float*)d_in[6];
    const float* wc1  = (const float*)d_in[7];
    const float* a11  = (const float*)d_in[8];
    const float* a21  = (const float*)d_in[9];
    const float* W2t  = (const float*)d_in[10];
    const float* w2_2 = (const float*)d_in[11];
    const float* w3_2 = (const float*)d_in[12];
    const float* wc2  = (const float*)d_in[13];
    const float* a12  = (const float*)d_in[14];
    const float* a22  = (const float*)d_in[15];
    const float* A1   = (const float*)d_in[16];
    const float* b1   = (const float*)d_in[17];
    const float* ln_g = (const float*)d_in[18];
    const float* ln_b = (const float*)d_in[19];
    const float* A2   = (const float*)d_in[20];
    const float* b2   = (const float*)d_in[21];
    float* outp = (float*)d_out;

    static bool attr_done = false;
    if (!attr_done) {
        cudaFuncSetAttribute((const void*)mma_gemm_k<false, 0, false>,
                             cudaFuncAttributeMaxDynamicSharedMemorySize, SMEMB);
        cudaFuncSetAttribute((const void*)mma_gemm_k<false, 0, true>,
                             cudaFuncAttributeMaxDynamicSharedMemorySize, SMEMB);
        cudaFuncSetAttribute((const void*)mma_gemm_k<false, 1, true>,
                             cudaFuncAttributeMaxDynamicSharedMemorySize, SMEMB);
        cudaFuncSetAttribute((const void*)mma_gemm_k<true, 0, false>,
                             cudaFuncAttributeMaxDynamicSharedMemorySize, SMEMB);
        attr_done = true;
    }

    float *hidden, *proj, *x4, *s1, *sn, *se, *y, *edge, *e4, *u2, *zpart,
          *invZe, *invZn, *x1, *xW, *sem, *comb, *hpre, *gc, *s1max, *snmax, *semax, *wt;
    cudaGetSymbolAddress((void**)&hidden, g_hidden);
    cudaGetSymbolAddress((void**)&proj,   g_proj);
    cudaGetSymbolAddress((void**)&x4,     g_x4);
    cudaGetSymbolAddress((void**)&s1,     g_s1);
    cudaGetSymbolAddress((void**)&sn,     g_sn);
    cudaGetSymbolAddress((void**)&se,     g_se);
    cudaGetSymbolAddress((void**)&y,      g_y);
    cudaGetSymbolAddress((void**)&edge,   g_edge);
    cudaGetSymbolAddress((void**)&e4,     g_e4);
    cudaGetSymbolAddress((void**)&u2,     g_u2);
    cudaGetSymbolAddress((void**)&zpart,  g_zpart);
    cudaGetSymbolAddress((void**)&invZe,  g_invZe);
    cudaGetSymbolAddress((void**)&invZn,  g_invZn);
    cudaGetSymbolAddress((void**)&x1,     g_x1);
    cudaGetSymbolAddress((void**)&xW,     g_xW);
    cudaGetSymbolAddress((void**)&sem,    g_sem);
    cudaGetSymbolAddress((void**)&comb,   g_comb);
    cudaGetSymbolAddress((void**)&hpre,   g_hpre);
    cudaGetSymbolAddress((void**)&gc,     g_c);
    cudaGetSymbolAddress((void**)&s1max,  g_s1max);
    cudaGetSymbolAddress((void**)&snmax,  g_snmax);
    cudaGetSymbolAddress((void**)&semax,  g_semax);
    cudaGetSymbolAddress((void**)&wt,     g_wt);

    float* Wpc  = wt;
    float* w21c = wt + 90000;
    float* w31c = wt + 180000;
    float* W2tc = wt + 270000;
    float* w22c = wt + 360000;
    float* w32c = wt + 450000;
    float* A1c  = wt + 540000;

    auto grid = [](int M, int N, int Z) {
        return dim3((N + 63) / 64, (M + 127) / 128, Z);
    };

    // tf32-round weights into scratch (idempotent, graph-capturable)
    cvt_k<<<(22500 + 255) / 256, 256>>>(Wp,   Wpc,  22500);
    cvt_k<<<(22500 + 255) / 256, 256>>>(w2_1, w21c, 22500);
    cvt_k<<<(22500 + 255) / 256, 256>>>(w3_1, w31c, 22500);
    cvt_k<<<(22500 + 255) / 256, 256>>>(W2t,  W2tc, 22500);
    cvt_k<<<(22500 + 255) / 256, 256>>>(w2_2, w22c, 22500);
    cvt_k<<<(22500 + 255) / 256, 256>>>(w3_2, w32c, 22500);
    cvt_k<<<(45000 + 255) / 256, 256>>>(A1,   A1c,  45000);

    dot_scalar_k<<<1, 128>>>(wc1, a11, gc + 0, Ff);
    dot_scalar_k<<<1, 128>>>(wc2, a12, gc + 1, HH);
    gather_k<<<ROWS, 128>>>(inp, emb, hidden);

    // proj = hidden @ Wp^T + bp
    mma_gemm_k<true, 0, false><<<grid(ROWS, HH, 1), 128, SMEMB>>>(
        hidden, Wpc, bp, nullptr, proj, ROWS, HH, Ff, Ff, Ff, HH, 0, 0, 0, 0);

    // ================= layer 1 (alpha 0.1, ELU, no transfer) =================
    mma_gemm_k<false, 0, false><<<grid(ROWS, Ff, 1), 128, SMEMB>>>(
        hidden, w21c, nullptr, nullptr, x4, ROWS, Ff, Ff, Ff, Ff, Ff, 0, 0, 0, 0);
    rowdots_k<<<ROWS, 128>>>(x4, a11 + Ff, a21, gc + 0, 0.1f, s1, sn, Ff);
    bmax_k<<<Bb, 256>>>(s1, s1max, Nn);
    bmax_k<<<Bb, 256>>>(sn, snmax, Nn);
    build_y_k<<<ROWS, 128>>>(hidden, s1, s1max, y);
    mma_gemm_k<false, 0, true><<<grid(Ee, YW, Bb), 128, SMEMB>>>(
        HT, y, nullptr, nullptr, edge, Ee, YW, Nn, Nn, YW, YW,
        (long)Ee * Nn, (long)Nn * YW, (long)Ee * YW, 0);
    invze_k<<<(EROWS + 255) / 256, 256>>>(edge, invZe);
    mma_gemm_k<false, 0, false><<<grid(EROWS, Ff, 1), 128, SMEMB>>>(
        edge, w31c, nullptr, invZe, e4, EROWS, Ff, Ff, YW, Ff, Ff, 0, 0, 0, 0);
    rowdot_k<<<EROWS, 128>>>(e4, a21 + Ff, se, Ff);
    bmax_k<<<Bb, 256>>>(se, semax, Ee);
    attn_build_k<<<dim3(Nn / 32, Ee / 32, Bb), dim3(32, 8)>>>(
        HT, sn, se, snmax, semax, invZe, u2, zpart, 0.1f);
    zsum_k<<<(ROWS + 255) / 256, 256>>>(zpart, invZn);
    mma_gemm_k<false, 1, true><<<grid(Nn, Ff, Bb), 128, SMEMB>>>(
        u2, edge, nullptr, invZn, x1, Nn, Ff, Ee, Ee, YW, Ff,
        (long)Nn * Ee, (long)Ee * YW, (long)Nn * Ff, Nn);

    // ================= layer 2 (alpha 0.2, no ELU, transfer W2t) =============
    mma_gemm_k<false, 0, false><<<grid(ROWS, HH, 1), 128, SMEMB>>>(
        x1, w22c, nullptr, nullptr, x4, ROWS, HH, Ff, Ff, HH, HH, 0, 0, 0, 0);
    mma_gemm_k<false, 0, false><<<grid(ROWS, HH, 1), 128, SMEMB>>>(
        x1, W2tc, nullptr, nullptr, xW, ROWS, HH, Ff, Ff, HH, HH, 0, 0, 0, 0);
    rowdots_k<<<ROWS, 128>>>(x4, a12 + HH, a22, gc + 1, 0.2f, s1, sn, HH);
    bmax_k<<<Bb, 256>>>(s1, s1max, Nn);
    bmax_k<<<Bb, 256>>>(sn, snmax, Nn);
    build_y_k<<<ROWS, 128>>>(xW, s1, s1max, y);
    mma_gemm_k<false, 0, true><<<grid(Ee, YW, Bb), 128, SMEMB>>>(
        HT, y, nullptr, nullptr, edge, Ee, YW, Nn, Nn, YW, YW,
        (long)Ee * Nn, (long)Nn * YW, (long)Ee * YW, 0);
    invze_k<<<(EROWS + 255) / 256, 256>>>(edge, invZe);
    mma_gemm_k<false, 0, false><<<grid(EROWS, HH, 1), 128, SMEMB>>>(
        edge, w32c, nullptr, invZe, e4, EROWS, HH, HH, YW, HH, HH, 0, 0, 0, 0);
    rowdot_k<<<EROWS, 128>>>(e4, a22 + HH, se, HH);
    bmax_k<<<Bb, 256>>>(se, semax, Ee);
    attn_build_k<<<dim3(Nn / 32, Ee / 32, Bb), dim3(32, 8)>>>(
        HT, sn, se, snmax, semax, invZe, u2, zpart, 0.2f);
    zsum_k<<<(ROWS + 255) / 256, 256>>>(zpart, invZn);
    mma_gemm_k<false, 0, false><<<grid(Nn, HH, Bb), 128, SMEMB>>>(
        u2, edge, nullptr, invZn, sem, Nn, HH, Ee, Ee, YW, HH,
        (long)Nn * Ee, (long)Ee * YW, (long)Nn * HH, Nn);

    // ================= head ==================================================
    concat_k<<<ROWS, 128>>>(proj, sem, comb);
    mma_gemm_k<true, 0, false><<<grid(ROWS, HH, 1), 128, SMEMB>>>(
        comb, A1c, b1, nullptr, hpre, ROWS, HH, 2 * HH, 2 * HH, 2 * HH, HH, 0, 0, 0, 0);
    final_k<<<ROWS, 128>>>(hpre, proj, sem, ln_g, ln_b, A2, b2, outp);
}